// round 1
// baseline (speedup 1.0000x reference)
#include <cuda_runtime.h>

#define D_MODEL 1024
#define N_HEADS 16
#define D_K     64
#define SEQ     2048
#define BSZ     2
#define M_TOK   (BSZ * SEQ)   // 4096 tokens

// Scratch (device globals: allocation-free rule)
__device__ float g_Q[M_TOK * D_MODEL];   // [b,h,s,d] layout, pre-scaled by 1/8
__device__ float g_K[M_TOK * D_MODEL];   // [b,h,s,d]
__device__ float g_V[M_TOK * D_MODEL];   // [b,h,s,d]
__device__ float g_O[M_TOK * D_MODEL];   // [b,s,h*d] concat layout

// ---------------------------------------------------------------------------
// SGEMM: C[m,n] = (sum_k A[m,k] * W[n,k] + bias[n]) * scale
// A: [M,1024] K-contig. W: [1024,1024] K-contig (row n = output feature).
// REMAP=1: write to [b,h,s,d] head layout. REMAP=0: plain [m,n].
// BM=BN=128, BK=16, 256 threads, 8x8 micro-tile.
// ---------------------------------------------------------------------------
template<int REMAP>
__global__ __launch_bounds__(256)
void sgemm_bias(const float* __restrict__ A, const float* __restrict__ W,
                const float* __restrict__ bias, float* __restrict__ C,
                float scale)
{
    const int BK = 16;
    __shared__ float As[BK][128];
    __shared__ float Bs[BK][128];

    const int bm = blockIdx.y * 128;
    const int bn = blockIdx.x * 128;
    const int tid = threadIdx.x;
    const int tx = tid & 15;    // 16 thread cols
    const int ty = tid >> 4;    // 16 thread rows

    float acc[8][8];
#pragma unroll
    for (int i = 0; i < 8; i++)
#pragma unroll
        for (int j = 0; j < 8; j++) acc[i][j] = 0.f;

    for (int k0 = 0; k0 < D_MODEL; k0 += BK) {
#pragma unroll
        for (int it = 0; it < 2; it++) {
            int idx = tid + it * 256;          // 0..511
            int row = idx >> 2;                // 0..127
            int kc  = (idx & 3) << 2;          // 0,4,8,12
            float4 va = *(const float4*)&A[(size_t)(bm + row) * D_MODEL + k0 + kc];
            As[kc + 0][row] = va.x; As[kc + 1][row] = va.y;
            As[kc + 2][row] = va.z; As[kc + 3][row] = va.w;
            float4 vb = *(const float4*)&W[(size_t)(bn + row) * D_MODEL + k0 + kc];
            Bs[kc + 0][row] = vb.x; Bs[kc + 1][row] = vb.y;
            Bs[kc + 2][row] = vb.z; Bs[kc + 3][row] = vb.w;
        }
        __syncthreads();

#pragma unroll
        for (int kk = 0; kk < BK; kk++) {
            float a[8], b[8];
            *(float4*)&a[0] = *(const float4*)&As[kk][ty * 8 + 0];
            *(float4*)&a[4] = *(const float4*)&As[kk][ty * 8 + 4];
            *(float4*)&b[0] = *(const float4*)&Bs[kk][tx * 8 + 0];
            *(float4*)&b[4] = *(const float4*)&Bs[kk][tx * 8 + 4];
#pragma unroll
            for (int i = 0; i < 8; i++)
#pragma unroll
                for (int j = 0; j < 8; j++)
                    acc[i][j] += a[i] * b[j];
        }
        __syncthreads();
    }

#pragma unroll
    for (int i = 0; i < 8; i++) {
        int m = bm + ty * 8 + i;
#pragma unroll
        for (int j = 0; j < 8; j++) {
            int n = bn + tx * 8 + j;
            float v = (acc[i][j] + bias[n]) * scale;
            if (REMAP) {
                int b = m >> 11, s = m & 2047;
                int h = n >> 6,  d = n & 63;
                C[((size_t)(b * N_HEADS + h) * SEQ + s) * D_K + d] = v;
            } else {
                C[(size_t)m * D_MODEL + n] = v;
            }
        }
    }
}

// ---------------------------------------------------------------------------
// Flash attention, fp32. One block = 64 query rows of one (b,h); one thread
// owns one query row (q + O accumulator in registers). K/V tiles in smem,
// read as broadcast float4 (all lanes same address -> no bank pressure).
// Scores staged in Ss[j][tid] (conflict-free). Online softmax.
// Q is pre-scaled by 1/sqrt(D_K). Output written in concat layout [b,s,h*d].
// ---------------------------------------------------------------------------
__global__ __launch_bounds__(64)
void flash_attn(const float* __restrict__ Q, const float* __restrict__ K,
                const float* __restrict__ V, float* __restrict__ O)
{
    __shared__ float Ks[64][64];
    __shared__ float Vs[64][64];
    __shared__ float Ss[64][64];   // Ss[j][tid]

    const int bh  = blockIdx.y;            // b*16 + h
    const int q0  = blockIdx.x * 64;
    const int tid = threadIdx.x;

    const float* Kb = K + (size_t)bh * SEQ * D_K;
    const float* Vb = V + (size_t)bh * SEQ * D_K;

    float4 q4[16];
    {
        const float* qrow = Q + ((size_t)bh * SEQ + q0 + tid) * D_K;
#pragma unroll
        for (int i = 0; i < 16; i++) q4[i] = *(const float4*)&qrow[i * 4];
    }

    float4 o4[16];
#pragma unroll
    for (int i = 0; i < 16; i++) o4[i] = make_float4(0.f, 0.f, 0.f, 0.f);
    float m = -1e30f, l = 0.f;

    for (int kv0 = 0; kv0 < SEQ; kv0 += 64) {
        __syncthreads();   // previous tile's Ks/Vs reads done
#pragma unroll
        for (int i = 0; i < 16; i++) {
            int idx = tid + i * 64;        // float4 index, 0..1023
            int r = idx >> 4;              // row 0..63
            int c = (idx & 15) << 2;       // col 0..60
            *(float4*)&Ks[r][c] = *(const float4*)&Kb[(size_t)(kv0 + r) * D_K + c];
            *(float4*)&Vs[r][c] = *(const float4*)&Vb[(size_t)(kv0 + r) * D_K + c];
        }
        __syncthreads();

        // --- scores: s[j] = q . K[j]  (4 independent FMA chains for ILP) ---
        float tmax = -1e30f;
        for (int j = 0; j < 64; j++) {
            float a0 = 0.f, a1 = 0.f, a2 = 0.f, a3 = 0.f;
#pragma unroll
            for (int i = 0; i < 16; i += 4) {
                float4 k0 = *(const float4*)&Ks[j][(i + 0) * 4];
                float4 k1 = *(const float4*)&Ks[j][(i + 1) * 4];
                float4 k2 = *(const float4*)&Ks[j][(i + 2) * 4];
                float4 k3 = *(const float4*)&Ks[j][(i + 3) * 4];
                a0 += q4[i + 0].x * k0.x + q4[i + 0].y * k0.y + q4[i + 0].z * k0.z + q4[i + 0].w * k0.w;
                a1 += q4[i + 1].x * k1.x + q4[i + 1].y * k1.y + q4[i + 1].z * k1.z + q4[i + 1].w * k1.w;
                a2 += q4[i + 2].x * k2.x + q4[i + 2].y * k2.y + q4[i + 2].z * k2.z + q4[i + 2].w * k2.w;
                a3 += q4[i + 3].x * k3.x + q4[i + 3].y * k3.y + q4[i + 3].z * k3.z + q4[i + 3].w * k3.w;
            }
            float s = (a0 + a1) + (a2 + a3);
            tmax = fmaxf(tmax, s);
            Ss[j][tid] = s;
        }

        // --- online softmax update ---
        float mnew = fmaxf(m, tmax);
        float corr = __expf(m - mnew);
        l *= corr;
#pragma unroll
        for (int i = 0; i < 16; i++) {
            o4[i].x *= corr; o4[i].y *= corr; o4[i].z *= corr; o4[i].w *= corr;
        }

        // --- P @ V ---
        for (int j = 0; j < 64; j++) {
            float p = __expf(Ss[j][tid] - mnew);
            l += p;
#pragma unroll
            for (int i = 0; i < 16; i++) {
                float4 vv = *(const float4*)&Vs[j][i * 4];
                o4[i].x += p * vv.x; o4[i].y += p * vv.y;
                o4[i].z += p * vv.z; o4[i].w += p * vv.w;
            }
        }
        m = mnew;
    }

    // normalize + write to concat layout [b, s, h*64 + d]
    float inv = 1.f / l;
    int b = bh >> 4, h = bh & 15;
    float* orow = O + ((size_t)(b * SEQ + q0 + tid)) * D_MODEL + h * D_K;
#pragma unroll
    for (int i = 0; i < 16; i++) {
        float4 v = o4[i];
        v.x *= inv; v.y *= inv; v.z *= inv; v.w *= inv;
        *(float4*)&orow[i * 4] = v;
    }
}

// ---------------------------------------------------------------------------
// Launch: 3 projections (head-remapped; Q pre-scaled by 1/8) -> flash -> out proj
// ---------------------------------------------------------------------------
extern "C" void kernel_launch(void* const* d_in, const int* in_sizes, int n_in,
                              void* d_out, int out_size)
{
    const float* q   = (const float*)d_in[0];
    const float* k   = (const float*)d_in[1];
    const float* v   = (const float*)d_in[2];
    const float* W_q = (const float*)d_in[3];
    const float* b_q = (const float*)d_in[4];
    const float* W_k = (const float*)d_in[5];
    const float* b_k = (const float*)d_in[6];
    const float* W_v = (const float*)d_in[7];
    const float* b_v = (const float*)d_in[8];
    const float* W_o = (const float*)d_in[9];
    const float* b_o = (const float*)d_in[10];
    float* out = (float*)d_out;

    float *gQ, *gK, *gV, *gO;
    cudaGetSymbolAddress((void**)&gQ, g_Q);
    cudaGetSymbolAddress((void**)&gK, g_K);
    cudaGetSymbolAddress((void**)&gV, g_V);
    cudaGetSymbolAddress((void**)&gO, g_O);

    dim3 ggrid(D_MODEL / 128, M_TOK / 128);   // (8, 32)
    const float inv_sqrt_dk = 0.125f;         // 1/sqrt(64)

    sgemm_bias<1><<<ggrid, 256>>>(q, W_q, b_q, gQ, inv_sqrt_dk);
    sgemm_bias<1><<<ggrid, 256>>>(k, W_k, b_k, gK, 1.0f);
    sgemm_bias<1><<<ggrid, 256>>>(v, W_v, b_v, gV, 1.0f);

    dim3 agrid(SEQ / 64, BSZ * N_HEADS);      // (32, 32)
    flash_attn<<<agrid, 64>>>(gQ, gK, gV, gO);

    sgemm_bias<0><<<ggrid, 256>>>(gO, W_o, b_o, out, 1.0f);
}

// round 3
// speedup vs baseline: 1.2346x; 1.2346x over previous
#include <cuda_runtime.h>
#include <cuda_fp16.h>
#include <cstdint>

#define D_MODEL 1024
#define N_HEADS 16
#define D_K     64
#define SEQ     2048
#define BSZ     2
#define M_TOK   (BSZ * SEQ)   // 4096 tokens

// ---------------------------------------------------------------------------
// Scratch (device globals: allocation-free rule)
// ---------------------------------------------------------------------------
__device__ float g_Q[M_TOK * D_MODEL];   // [b,h,s,d], pre-scaled by 1/8
__device__ float g_K[M_TOK * D_MODEL];   // [b,h,s,d]
__device__ float g_V[M_TOK * D_MODEL];   // [b,h,s,d]
__device__ float g_O[M_TOK * D_MODEL];   // [b,s,h*d] concat layout

// fp16 arena: split (hi/lo) copies of activations + weights
#define MEG (1048576ULL)
__device__ __half g_hf[40 * MEG];

static const size_t OFF_QH = 0,         OFF_QL = 4 * MEG;
static const size_t OFF_KH = 8 * MEG,   OFF_KL = 12 * MEG;
static const size_t OFF_VH = 16 * MEG,  OFF_VL = 20 * MEG;
static const size_t OFF_WQH = 24 * MEG, OFF_WQL = 25 * MEG;
static const size_t OFF_WKH = 26 * MEG, OFF_WKL = 27 * MEG;
static const size_t OFF_WVH = 28 * MEG, OFF_WVL = 29 * MEG;
static const size_t OFF_WOH = 30 * MEG, OFF_WOL = 31 * MEG;
static const size_t OFF_OH = 32 * MEG,  OFF_OL = 36 * MEG;

// ---------------------------------------------------------------------------
// mma.sync / ldmatrix wrappers (baseline PTX — compiles at compute_103)
// ---------------------------------------------------------------------------
__device__ __forceinline__ uint32_t smem_u32(const void* p) {
    uint32_t a;
    asm("{ .reg .u64 t; cvta.to.shared.u64 t, %1; cvt.u32.u64 %0, t; }"
        : "=r"(a) : "l"(p));
    return a;
}

__device__ __forceinline__ void ldsm_x4(uint32_t* r, uint32_t addr) {
    asm volatile("ldmatrix.sync.aligned.m8n8.x4.shared.b16 {%0,%1,%2,%3}, [%4];"
                 : "=r"(r[0]), "=r"(r[1]), "=r"(r[2]), "=r"(r[3]) : "r"(addr));
}
__device__ __forceinline__ void ldsm_x2(uint32_t* r, uint32_t addr) {
    asm volatile("ldmatrix.sync.aligned.m8n8.x2.shared.b16 {%0,%1}, [%2];"
                 : "=r"(r[0]), "=r"(r[1]) : "r"(addr));
}
__device__ __forceinline__ void mma16816(float* d, const uint32_t* a, const uint32_t* b) {
    asm volatile(
        "mma.sync.aligned.m16n8k16.row.col.f32.f16.f16.f32 "
        "{%0,%1,%2,%3}, {%4,%5,%6,%7}, {%8,%9}, {%0,%1,%2,%3};"
        : "+f"(d[0]), "+f"(d[1]), "+f"(d[2]), "+f"(d[3])
        : "r"(a[0]), "r"(a[1]), "r"(a[2]), "r"(a[3]), "r"(b[0]), "r"(b[1]));
}

// ---------------------------------------------------------------------------
// split: fp32 -> (hi fp16, lo fp16),  x = hi + lo + O(2^-24)
// ---------------------------------------------------------------------------
__global__ __launch_bounds__(256)
void split_f16(const float* __restrict__ x, __half* __restrict__ hi,
               __half* __restrict__ lo, int n4)
{
    int i = blockIdx.x * blockDim.x + threadIdx.x;
    if (i >= n4) return;
    float4 v = ((const float4*)x)[i];
    __half h0 = __float2half_rn(v.x);
    __half h1 = __float2half_rn(v.y);
    __half h2 = __float2half_rn(v.z);
    __half h3 = __float2half_rn(v.w);
    __half l0 = __float2half_rn(v.x - __half2float(h0));
    __half l1 = __float2half_rn(v.y - __half2float(h1));
    __half l2 = __float2half_rn(v.z - __half2float(h2));
    __half l3 = __float2half_rn(v.w - __half2float(h3));
    __half2 ph0; ph0.x = h0; ph0.y = h1;
    __half2 ph1; ph1.x = h2; ph1.y = h3;
    __half2 pl0; pl0.x = l0; pl0.y = l1;
    __half2 pl1; pl1.x = l2; pl1.y = l3;
    ((__half2*)hi)[i * 2 + 0] = ph0;
    ((__half2*)hi)[i * 2 + 1] = ph1;
    ((__half2*)lo)[i * 2 + 0] = pl0;
    ((__half2*)lo)[i * 2 + 1] = pl1;
}

// ---------------------------------------------------------------------------
// Tensor-core split-fp16 GEMM:  C[m,n] = (sum_k A[m,k]*W[n,k] + bias[n]) * scale
// D(fp32 regs) += Ahi*Whi + Alo*Whi + Ahi*Wlo
// CTA tile 128x128, BK=32, 256 threads, warp tile 64(m)x32(n).
// Smem rows padded to 40 halves (80B = 5*16B): ldmatrix conflict-free + aligned.
// ---------------------------------------------------------------------------
#define SP 40   // smem row stride in halves

template<int REMAP>
__global__ __launch_bounds__(256)
void gemm_mma(const __half* __restrict__ Ahi, const __half* __restrict__ Alo,
              const __half* __restrict__ Bhi, const __half* __restrict__ Blo,
              const float* __restrict__ bias, float* __restrict__ C, float scale)
{
    __shared__ __align__(16) __half sAh[128 * SP];
    __shared__ __align__(16) __half sAl[128 * SP];
    __shared__ __align__(16) __half sBh[128 * SP];
    __shared__ __align__(16) __half sBl[128 * SP];

    const int tid  = threadIdx.x;
    const int wid  = tid >> 5;
    const int lane = tid & 31;
    const int bm = blockIdx.y * 128;
    const int bn = blockIdx.x * 128;
    const int wm = (wid >> 2) * 64;     // warp grid 2(m) x 4(n)
    const int wn = (wid & 3) * 32;

    float acc[4][4][4];
#pragma unroll
    for (int i = 0; i < 4; i++)
#pragma unroll
        for (int j = 0; j < 4; j++)
#pragma unroll
            for (int r = 0; r < 4; r++) acc[i][j][r] = 0.f;

    // Fragment smem addresses (byte addresses for ldmatrix)
    const uint32_t uAh = smem_u32(sAh), uAl = smem_u32(sAl);
    const uint32_t uBh = smem_u32(sBh), uBl = smem_u32(sBl);
    const int arow = lane & 15;            // A: row within 16-row tile
    const int acol = (lane >> 4) * 8;      // A: 8-half column group
    const int brow = lane & 7;             // B: n within 8
    const int bcol = ((lane & 15) >> 3) * 8;

    for (int kc = 0; kc < 32; kc++) {
        const int k0 = kc * 32;
        __syncthreads();   // previous iter's frags consumed
#pragma unroll
        for (int j = 0; j < 2; j++) {
            int c   = tid + j * 256;       // chunk 0..511
            int row = c >> 2;
            int kcol = (c & 3) * 8;        // halves
            size_t ga = (size_t)(bm + row) * D_MODEL + k0 + kcol;
            size_t gb = (size_t)(bn + row) * D_MODEL + k0 + kcol;
            int so = row * SP + kcol;
            *(uint4*)&sAh[so] = *(const uint4*)&Ahi[ga];
            *(uint4*)&sAl[so] = *(const uint4*)&Alo[ga];
            *(uint4*)&sBh[so] = *(const uint4*)&Bhi[gb];
            *(uint4*)&sBl[so] = *(const uint4*)&Blo[gb];
        }
        __syncthreads();

#pragma unroll
        for (int ks = 0; ks < 2; ks++) {
            uint32_t ah[4][4], al[4][4];
#pragma unroll
            for (int mt = 0; mt < 4; mt++) {
                uint32_t off = ((wm + mt * 16 + arow) * SP + ks * 16 + acol) * 2;
                ldsm_x4(ah[mt], uAh + off);
                ldsm_x4(al[mt], uAl + off);
            }
            uint32_t bh[4][2];
#pragma unroll
            for (int nt = 0; nt < 4; nt++) {
                uint32_t off = ((wn + nt * 8 + brow) * SP + ks * 16 + bcol) * 2;
                ldsm_x2(bh[nt], uBh + off);
            }
#pragma unroll
            for (int mt = 0; mt < 4; mt++)
#pragma unroll
                for (int nt = 0; nt < 4; nt++) {
                    mma16816(acc[mt][nt], ah[mt], bh[nt]);
                    mma16816(acc[mt][nt], al[mt], bh[nt]);
                }
            uint32_t bl[4][2];
#pragma unroll
            for (int nt = 0; nt < 4; nt++) {
                uint32_t off = ((wn + nt * 8 + brow) * SP + ks * 16 + bcol) * 2;
                ldsm_x2(bl[nt], uBl + off);
            }
#pragma unroll
            for (int mt = 0; mt < 4; mt++)
#pragma unroll
                for (int nt = 0; nt < 4; nt++)
                    mma16816(acc[mt][nt], ah[mt], bl[nt]);
        }
    }

    // Epilogue: D frag lane mapping: rows l/4 and l/4+8; cols 2(l%4)+{0,1}
#pragma unroll
    for (int mt = 0; mt < 4; mt++) {
#pragma unroll
        for (int half = 0; half < 2; half++) {
            int m = bm + wm + mt * 16 + (lane >> 2) + half * 8;
            int b = m >> 11, s = m & 2047;
#pragma unroll
            for (int nt = 0; nt < 4; nt++) {
                int n = bn + wn + nt * 8 + 2 * (lane & 3);
                float2 v;
                v.x = (acc[mt][nt][half * 2 + 0] + bias[n + 0]) * scale;
                v.y = (acc[mt][nt][half * 2 + 1] + bias[n + 1]) * scale;
                if (REMAP) {
                    int h = n >> 6, dd = n & 63;
                    *(float2*)&C[((size_t)(b * N_HEADS + h) * SEQ + s) * D_K + dd] = v;
                } else {
                    *(float2*)&C[(size_t)m * D_MODEL + n] = v;
                }
            }
        }
    }
}

// ---------------------------------------------------------------------------
// Flash attention, fp32 (unchanged — tensor-core conversion next round)
// ---------------------------------------------------------------------------
__global__ __launch_bounds__(64)
void flash_attn(const float* __restrict__ Q, const float* __restrict__ K,
                const float* __restrict__ V, float* __restrict__ O)
{
    __shared__ float Ks[64][64];
    __shared__ float Vs[64][64];
    __shared__ float Ss[64][64];

    const int bh  = blockIdx.y;
    const int q0  = blockIdx.x * 64;
    const int tid = threadIdx.x;

    const float* Kb = K + (size_t)bh * SEQ * D_K;
    const float* Vb = V + (size_t)bh * SEQ * D_K;

    float4 q4[16];
    {
        const float* qrow = Q + ((size_t)bh * SEQ + q0 + tid) * D_K;
#pragma unroll
        for (int i = 0; i < 16; i++) q4[i] = *(const float4*)&qrow[i * 4];
    }

    float4 o4[16];
#pragma unroll
    for (int i = 0; i < 16; i++) o4[i] = make_float4(0.f, 0.f, 0.f, 0.f);
    float m = -1e30f, l = 0.f;

    for (int kv0 = 0; kv0 < SEQ; kv0 += 64) {
        __syncthreads();
#pragma unroll
        for (int i = 0; i < 16; i++) {
            int idx = tid + i * 64;
            int r = idx >> 4;
            int c = (idx & 15) << 2;
            *(float4*)&Ks[r][c] = *(const float4*)&Kb[(size_t)(kv0 + r) * D_K + c];
            *(float4*)&Vs[r][c] = *(const float4*)&Vb[(size_t)(kv0 + r) * D_K + c];
        }
        __syncthreads();

        float tmax = -1e30f;
        for (int j = 0; j < 64; j++) {
            float a0 = 0.f, a1 = 0.f, a2 = 0.f, a3 = 0.f;
#pragma unroll
            for (int i = 0; i < 16; i += 4) {
                float4 k0 = *(const float4*)&Ks[j][(i + 0) * 4];
                float4 k1 = *(const float4*)&Ks[j][(i + 1) * 4];
                float4 k2 = *(const float4*)&Ks[j][(i + 2) * 4];
                float4 k3 = *(const float4*)&Ks[j][(i + 3) * 4];
                a0 += q4[i + 0].x * k0.x + q4[i + 0].y * k0.y + q4[i + 0].z * k0.z + q4[i + 0].w * k0.w;
                a1 += q4[i + 1].x * k1.x + q4[i + 1].y * k1.y + q4[i + 1].z * k1.z + q4[i + 1].w * k1.w;
                a2 += q4[i + 2].x * k2.x + q4[i + 2].y * k2.y + q4[i + 2].z * k2.z + q4[i + 2].w * k2.w;
                a3 += q4[i + 3].x * k3.x + q4[i + 3].y * k3.y + q4[i + 3].z * k3.z + q4[i + 3].w * k3.w;
            }
            float sv = (a0 + a1) + (a2 + a3);
            tmax = fmaxf(tmax, sv);
            Ss[j][tid] = sv;
        }

        float mnew = fmaxf(m, tmax);
        float corr = __expf(m - mnew);
        l *= corr;
#pragma unroll
        for (int i = 0; i < 16; i++) {
            o4[i].x *= corr; o4[i].y *= corr; o4[i].z *= corr; o4[i].w *= corr;
        }

        for (int j = 0; j < 64; j++) {
            float p = __expf(Ss[j][tid] - mnew);
            l += p;
#pragma unroll
            for (int i = 0; i < 16; i++) {
                float4 vv = *(const float4*)&Vs[j][i * 4];
                o4[i].x += p * vv.x; o4[i].y += p * vv.y;
                o4[i].z += p * vv.z; o4[i].w += p * vv.w;
            }
        }
        m = mnew;
    }

    float inv = 1.f / l;
    int b = bh >> 4, h = bh & 15;
    float* orow = O + ((size_t)(b * SEQ + q0 + tid)) * D_MODEL + h * D_K;
#pragma unroll
    for (int i = 0; i < 16; i++) {
        float4 v = o4[i];
        v.x *= inv; v.y *= inv; v.z *= inv; v.w *= inv;
        *(float4*)&orow[i * 4] = v;
    }
}

// ---------------------------------------------------------------------------
// Launch
// ---------------------------------------------------------------------------
extern "C" void kernel_launch(void* const* d_in, const int* in_sizes, int n_in,
                              void* d_out, int out_size)
{
    const float* q   = (const float*)d_in[0];
    const float* k   = (const float*)d_in[1];
    const float* v   = (const float*)d_in[2];
    const float* W_q = (const float*)d_in[3];
    const float* b_q = (const float*)d_in[4];
    const float* W_k = (const float*)d_in[5];
    const float* b_k = (const float*)d_in[6];
    const float* W_v = (const float*)d_in[7];
    const float* b_v = (const float*)d_in[8];
    const float* W_o = (const float*)d_in[9];
    const float* b_o = (const float*)d_in[10];
    float* out = (float*)d_out;

    float *gQ, *gK, *gV, *gO;
    __half* hf;
    cudaGetSymbolAddress((void**)&gQ, g_Q);
    cudaGetSymbolAddress((void**)&gK, g_K);
    cudaGetSymbolAddress((void**)&gV, g_V);
    cudaGetSymbolAddress((void**)&gO, g_O);
    cudaGetSymbolAddress((void**)&hf, g_hf);

    const int n4_act = M_TOK * D_MODEL / 4;     // 1048576
    const int n4_w   = D_MODEL * D_MODEL / 4;   // 262144

    split_f16<<<n4_act / 256, 256>>>(q, hf + OFF_QH, hf + OFF_QL, n4_act);
    split_f16<<<n4_act / 256, 256>>>(k, hf + OFF_KH, hf + OFF_KL, n4_act);
    split_f16<<<n4_act / 256, 256>>>(v, hf + OFF_VH, hf + OFF_VL, n4_act);
    split_f16<<<n4_w / 256, 256>>>(W_q, hf + OFF_WQH, hf + OFF_WQL, n4_w);
    split_f16<<<n4_w / 256, 256>>>(W_k, hf + OFF_WKH, hf + OFF_WKL, n4_w);
    split_f16<<<n4_w / 256, 256>>>(W_v, hf + OFF_WVH, hf + OFF_WVL, n4_w);
    split_f16<<<n4_w / 256, 256>>>(W_o, hf + OFF_WOH, hf + OFF_WOL, n4_w);

    dim3 ggrid(D_MODEL / 128, M_TOK / 128);   // (8, 32)
    gemm_mma<1><<<ggrid, 256>>>(hf + OFF_QH, hf + OFF_QL,
                                hf + OFF_WQH, hf + OFF_WQL, b_q, gQ, 0.125f);
    gemm_mma<1><<<ggrid, 256>>>(hf + OFF_KH, hf + OFF_KL,
                                hf + OFF_WKH, hf + OFF_WKL, b_k, gK, 1.0f);
    gemm_mma<1><<<ggrid, 256>>>(hf + OFF_VH, hf + OFF_VL,
                                hf + OFF_WVH, hf + OFF_WVL, b_v, gV, 1.0f);

    dim3 agrid(SEQ / 64, BSZ * N_HEADS);      // (32, 32)
    flash_attn<<<agrid, 64>>>(gQ, gK, gV, gO);

    split_f16<<<n4_act / 256, 256>>>(gO, hf + OFF_OH, hf + OFF_OL, n4_act);
    gemm_mma<0><<<ggrid, 256>>>(hf + OFF_OH, hf + OFF_OL,
                                hf + OFF_WOH, hf + OFF_WOL, b_o, out, 1.0f);
}

// round 4
// speedup vs baseline: 2.5602x; 2.0737x over previous
#include <cuda_runtime.h>
#include <cuda_fp16.h>
#include <cstdint>

#define D_MODEL 1024
#define N_HEADS 16
#define D_K     64
#define SEQ     2048
#define BSZ     2
#define M_TOK   (BSZ * SEQ)   // 4096 tokens

// ---------------------------------------------------------------------------
// fp16 arena (device global: allocation-free rule). 64M halves = 128 MB.
// ---------------------------------------------------------------------------
#define MEG (1048576ULL)
__device__ __half g_hf[64 * MEG];

// input splits (A operands of QKV projections), [b,s,1024]
static const size_t OFF_IQH = 0,        OFF_IQL = 4 * MEG;
static const size_t OFF_IKH = 8 * MEG,  OFF_IKL = 12 * MEG;
static const size_t OFF_IVH = 16 * MEG, OFF_IVL = 20 * MEG;
// weight splits
static const size_t OFF_WQH = 24 * MEG, OFF_WQL = 25 * MEG;
static const size_t OFF_WKH = 26 * MEG, OFF_WKL = 27 * MEG;
static const size_t OFF_WVH = 28 * MEG, OFF_WVL = 29 * MEG;
static const size_t OFF_WOH = 30 * MEG, OFF_WOL = 31 * MEG;
// projected Q/K/V hi/lo, [b,h,s,d]
static const size_t OFF_PQH = 32 * MEG, OFF_PQL = 36 * MEG;
static const size_t OFF_PKH = 40 * MEG, OFF_PKL = 44 * MEG;
static const size_t OFF_PVH = 48 * MEG, OFF_PVL = 52 * MEG;
// attention output hi/lo, [b,s,h*d] concat
static const size_t OFF_OH = 56 * MEG,  OFF_OL = 60 * MEG;

// ---------------------------------------------------------------------------
// mma.sync / ldmatrix wrappers (baseline PTX — compiles at compute_103)
// ---------------------------------------------------------------------------
__device__ __forceinline__ uint32_t smem_u32(const void* p) {
    uint32_t a;
    asm("{ .reg .u64 t; cvta.to.shared.u64 t, %1; cvt.u32.u64 %0, t; }"
        : "=r"(a) : "l"(p));
    return a;
}
__device__ __forceinline__ void ldsm_x4(uint32_t* r, uint32_t addr) {
    asm volatile("ldmatrix.sync.aligned.m8n8.x4.shared.b16 {%0,%1,%2,%3}, [%4];"
                 : "=r"(r[0]), "=r"(r[1]), "=r"(r[2]), "=r"(r[3]) : "r"(addr));
}
__device__ __forceinline__ void ldsm_x2(uint32_t* r, uint32_t addr) {
    asm volatile("ldmatrix.sync.aligned.m8n8.x2.shared.b16 {%0,%1}, [%2];"
                 : "=r"(r[0]), "=r"(r[1]) : "r"(addr));
}
__device__ __forceinline__ void ldsm_x2_t(uint32_t* r, uint32_t addr) {
    asm volatile("ldmatrix.sync.aligned.m8n8.x2.trans.shared.b16 {%0,%1}, [%2];"
                 : "=r"(r[0]), "=r"(r[1]) : "r"(addr));
}
__device__ __forceinline__ void mma16816(float* d, const uint32_t* a, const uint32_t* b) {
    asm volatile(
        "mma.sync.aligned.m16n8k16.row.col.f32.f16.f16.f32 "
        "{%0,%1,%2,%3}, {%4,%5,%6,%7}, {%8,%9}, {%0,%1,%2,%3};"
        : "+f"(d[0]), "+f"(d[1]), "+f"(d[2]), "+f"(d[3])
        : "r"(a[0]), "r"(a[1]), "r"(a[2]), "r"(a[3]), "r"(b[0]), "r"(b[1]));
}

// ---------------------------------------------------------------------------
// split: fp32 -> (hi fp16, lo fp16)
// ---------------------------------------------------------------------------
__global__ __launch_bounds__(256)
void split_f16(const float* __restrict__ x, __half* __restrict__ hi,
               __half* __restrict__ lo, int n4)
{
    int i = blockIdx.x * blockDim.x + threadIdx.x;
    if (i >= n4) return;
    float4 v = ((const float4*)x)[i];
    __half h0 = __float2half_rn(v.x), h1 = __float2half_rn(v.y);
    __half h2 = __float2half_rn(v.z), h3 = __float2half_rn(v.w);
    __half2 ph0; ph0.x = h0; ph0.y = h1;
    __half2 ph1; ph1.x = h2; ph1.y = h3;
    __half2 pl0; pl0.x = __float2half_rn(v.x - __half2float(h0));
    pl0.y = __float2half_rn(v.y - __half2float(h1));
    __half2 pl1; pl1.x = __float2half_rn(v.z - __half2float(h2));
    pl1.y = __float2half_rn(v.w - __half2float(h3));
    ((__half2*)hi)[i * 2 + 0] = ph0;
    ((__half2*)hi)[i * 2 + 1] = ph1;
    ((__half2*)lo)[i * 2 + 0] = pl0;
    ((__half2*)lo)[i * 2 + 1] = pl1;
}

// ---------------------------------------------------------------------------
// Tensor-core split-fp16 GEMM.
// MODE 0: fp32 output, plain [m,n] (final O-projection).
// MODE 1: fp16 hi/lo output, head-remapped to [b,h,s,d] (QKV projections).
// CTA 128x128, BK=32, 256 threads, warp tile 64x32.
// ---------------------------------------------------------------------------
#define SP 40   // smem row stride in halves (80B = 5x16B, ldmatrix conflict-free)

template<int MODE>
__global__ __launch_bounds__(256)
void gemm_mma(const __half* __restrict__ Ahi, const __half* __restrict__ Alo,
              const __half* __restrict__ Bhi, const __half* __restrict__ Blo,
              const float* __restrict__ bias, float* __restrict__ C,
              __half* __restrict__ Ch, __half* __restrict__ Cl, float scale)
{
    __shared__ __align__(16) __half sAh[128 * SP];
    __shared__ __align__(16) __half sAl[128 * SP];
    __shared__ __align__(16) __half sBh[128 * SP];
    __shared__ __align__(16) __half sBl[128 * SP];

    const int tid  = threadIdx.x;
    const int wid  = tid >> 5;
    const int lane = tid & 31;
    const int bm = blockIdx.y * 128;
    const int bn = blockIdx.x * 128;
    const int wm = (wid >> 2) * 64;
    const int wn = (wid & 3) * 32;

    float acc[4][4][4];
#pragma unroll
    for (int i = 0; i < 4; i++)
#pragma unroll
        for (int j = 0; j < 4; j++)
#pragma unroll
            for (int r = 0; r < 4; r++) acc[i][j][r] = 0.f;

    const uint32_t uAh = smem_u32(sAh), uAl = smem_u32(sAl);
    const uint32_t uBh = smem_u32(sBh), uBl = smem_u32(sBl);
    const int arow = lane & 15;
    const int acol = (lane >> 4) * 8;
    const int brow = lane & 7;
    const int bcol = ((lane & 15) >> 3) * 8;

    for (int kc = 0; kc < 32; kc++) {
        const int k0 = kc * 32;
        __syncthreads();
#pragma unroll
        for (int j = 0; j < 2; j++) {
            int c    = tid + j * 256;
            int row  = c >> 2;
            int kcol = (c & 3) * 8;
            size_t ga = (size_t)(bm + row) * D_MODEL + k0 + kcol;
            size_t gb = (size_t)(bn + row) * D_MODEL + k0 + kcol;
            int so = row * SP + kcol;
            *(uint4*)&sAh[so] = *(const uint4*)&Ahi[ga];
            *(uint4*)&sAl[so] = *(const uint4*)&Alo[ga];
            *(uint4*)&sBh[so] = *(const uint4*)&Bhi[gb];
            *(uint4*)&sBl[so] = *(const uint4*)&Blo[gb];
        }
        __syncthreads();

#pragma unroll
        for (int ks = 0; ks < 2; ks++) {
            uint32_t ah[4][4], al[4][4];
#pragma unroll
            for (int mt = 0; mt < 4; mt++) {
                uint32_t off = ((wm + mt * 16 + arow) * SP + ks * 16 + acol) * 2;
                ldsm_x4(ah[mt], uAh + off);
                ldsm_x4(al[mt], uAl + off);
            }
            uint32_t bh[4][2];
#pragma unroll
            for (int nt = 0; nt < 4; nt++) {
                uint32_t off = ((wn + nt * 8 + brow) * SP + ks * 16 + bcol) * 2;
                ldsm_x2(bh[nt], uBh + off);
            }
#pragma unroll
            for (int mt = 0; mt < 4; mt++)
#pragma unroll
                for (int nt = 0; nt < 4; nt++) {
                    mma16816(acc[mt][nt], ah[mt], bh[nt]);
                    mma16816(acc[mt][nt], al[mt], bh[nt]);
                }
            uint32_t bl[4][2];
#pragma unroll
            for (int nt = 0; nt < 4; nt++) {
                uint32_t off = ((wn + nt * 8 + brow) * SP + ks * 16 + bcol) * 2;
                ldsm_x2(bl[nt], uBl + off);
            }
#pragma unroll
            for (int mt = 0; mt < 4; mt++)
#pragma unroll
                for (int nt = 0; nt < 4; nt++)
                    mma16816(acc[mt][nt], ah[mt], bl[nt]);
        }
    }

#pragma unroll
    for (int mt = 0; mt < 4; mt++) {
#pragma unroll
        for (int half = 0; half < 2; half++) {
            int m = bm + wm + mt * 16 + (lane >> 2) + half * 8;
            int b = m >> 11, s = m & 2047;
#pragma unroll
            for (int nt = 0; nt < 4; nt++) {
                int n = bn + wn + nt * 8 + 2 * (lane & 3);
                float vx = (acc[mt][nt][half * 2 + 0] + bias[n + 0]) * scale;
                float vy = (acc[mt][nt][half * 2 + 1] + bias[n + 1]) * scale;
                if (MODE == 1) {
                    int h = n >> 6, dd = n & 63;
                    size_t co = ((size_t)(b * N_HEADS + h) * SEQ + s) * D_K + dd;
                    __half hx = __float2half_rn(vx), hy = __float2half_rn(vy);
                    __half2 hh; hh.x = hx; hh.y = hy;
                    __half2 ll;
                    ll.x = __float2half_rn(vx - __half2float(hx));
                    ll.y = __float2half_rn(vy - __half2float(hy));
                    *(__half2*)&Ch[co] = hh;
                    *(__half2*)&Cl[co] = ll;
                } else {
                    float2 v; v.x = vx; v.y = vy;
                    *(float2*)&C[(size_t)m * D_MODEL + n] = v;
                }
            }
        }
    }
}

// ---------------------------------------------------------------------------
// Flash attention, mma.sync fp16-split, FA2 register path.
// Block = 128 threads (4 warps), 64 q-rows per CTA (16 per warp), KV tiles 64.
// Q pre-scaled by 0.125*log2e in projection -> softmax uses exp2f.
// ---------------------------------------------------------------------------
#define ST 72   // kv-tile smem stride in halves (144B = 9x16B)

__global__ __launch_bounds__(128)
void flash_mma(const __half* __restrict__ Qh, const __half* __restrict__ Ql,
               const __half* __restrict__ Kh, const __half* __restrict__ Kl,
               const __half* __restrict__ Vh, const __half* __restrict__ Vl,
               __half* __restrict__ Oh, __half* __restrict__ Ol)
{
    __shared__ __align__(16) __half sKh[64 * ST];
    __shared__ __align__(16) __half sKl[64 * ST];
    __shared__ __align__(16) __half sVh[64 * ST];
    __shared__ __align__(16) __half sVl[64 * ST];

    const int bh  = blockIdx.y;
    const int q0  = blockIdx.x * 64;
    const int tid = threadIdx.x;
    const int w   = tid >> 5;
    const int lane = tid & 31;
    const size_t bhoff = (size_t)bh * SEQ * D_K;

    const uint32_t uKh = smem_u32(sKh), uKl = smem_u32(sKl);
    const uint32_t uVh = smem_u32(sVh), uVl = smem_u32(sVl);

    // ---- stage Q (reuse K smem), extract A-fragments ----
#pragma unroll
    for (int it = 0; it < 4; it++) {
        int idx = tid + it * 128;
        int row = idx >> 3, c8 = (idx & 7) * 8;
        size_t g = bhoff + (size_t)(q0 + row) * D_K + c8;
        *(uint4*)&sKh[row * ST + c8] = *(const uint4*)&Qh[g];
        *(uint4*)&sKl[row * ST + c8] = *(const uint4*)&Ql[g];
    }
    __syncthreads();
    uint32_t qh[4][4], ql[4][4];
    {
        const int arow = lane & 15, acol = (lane >> 4) * 8;
#pragma unroll
        for (int ks = 0; ks < 4; ks++) {
            uint32_t off = ((w * 16 + arow) * ST + ks * 16 + acol) * 2;
            ldsm_x4(qh[ks], uKh + off);
            ldsm_x4(ql[ks], uKl + off);
        }
    }

    float o[8][4];
#pragma unroll
    for (int i = 0; i < 8; i++)
#pragma unroll
        for (int r = 0; r < 4; r++) o[i][r] = 0.f;
    float mA = -1e30f, mB = -1e30f, lA = 0.f, lB = 0.f;

    for (int kv0 = 0; kv0 < SEQ; kv0 += 64) {
        __syncthreads();   // previous iter's smem reads (and Q frag reads) done
#pragma unroll
        for (int it = 0; it < 4; it++) {
            int idx = tid + it * 128;
            int row = idx >> 3, c8 = (idx & 7) * 8;
            size_t g = bhoff + (size_t)(kv0 + row) * D_K + c8;
            int so = row * ST + c8;
            *(uint4*)&sKh[so] = *(const uint4*)&Kh[g];
            *(uint4*)&sKl[so] = *(const uint4*)&Kl[g];
            *(uint4*)&sVh[so] = *(const uint4*)&Vh[g];
            *(uint4*)&sVl[so] = *(const uint4*)&Vl[g];
        }
        __syncthreads();

        // ---- S = Q . K^T (split, fp32 accum) ----
        float s[8][4];
#pragma unroll
        for (int i = 0; i < 8; i++)
#pragma unroll
            for (int r = 0; r < 4; r++) s[i][r] = 0.f;

        const int brow = lane & 7;
        const int bcol = ((lane & 15) >> 3) * 8;
#pragma unroll
        for (int ks = 0; ks < 4; ks++) {
            uint32_t kh[8][2], kl[8][2];
#pragma unroll
            for (int nt = 0; nt < 8; nt++) {
                uint32_t off = ((nt * 8 + brow) * ST + ks * 16 + bcol) * 2;
                ldsm_x2(kh[nt], uKh + off);
                ldsm_x2(kl[nt], uKl + off);
            }
#pragma unroll
            for (int nt = 0; nt < 8; nt++) mma16816(s[nt], qh[ks], kh[nt]);
#pragma unroll
            for (int nt = 0; nt < 8; nt++) mma16816(s[nt], ql[ks], kh[nt]);
#pragma unroll
            for (int nt = 0; nt < 8; nt++) mma16816(s[nt], qh[ks], kl[nt]);
        }

        // ---- online softmax (log2 domain) ----
        float tA = -1e30f, tB = -1e30f;
#pragma unroll
        for (int nt = 0; nt < 8; nt++) {
            tA = fmaxf(tA, fmaxf(s[nt][0], s[nt][1]));
            tB = fmaxf(tB, fmaxf(s[nt][2], s[nt][3]));
        }
        tA = fmaxf(tA, __shfl_xor_sync(0xffffffff, tA, 1));
        tA = fmaxf(tA, __shfl_xor_sync(0xffffffff, tA, 2));
        tB = fmaxf(tB, __shfl_xor_sync(0xffffffff, tB, 1));
        tB = fmaxf(tB, __shfl_xor_sync(0xffffffff, tB, 2));
        float mnA = fmaxf(mA, tA), mnB = fmaxf(mB, tB);
        float cA = exp2f(mA - mnA), cB = exp2f(mB - mnB);
        lA *= cA; lB *= cB;
#pragma unroll
        for (int nt = 0; nt < 8; nt++) {
            o[nt][0] *= cA; o[nt][1] *= cA;
            o[nt][2] *= cB; o[nt][3] *= cB;
        }
        mA = mnA; mB = mnB;

        // ---- P = exp2(S - m), split to hi/lo A-fragments in registers ----
        uint32_t pAh[8], pAl[8], pBh[8], pBl[8];
#pragma unroll
        for (int nt = 0; nt < 8; nt++) {
            float p0 = exp2f(s[nt][0] - mnA);
            float p1 = exp2f(s[nt][1] - mnA);
            float p2 = exp2f(s[nt][2] - mnB);
            float p3 = exp2f(s[nt][3] - mnB);
            lA += p0 + p1; lB += p2 + p3;
            __half h0 = __float2half_rn(p0), h1 = __float2half_rn(p1);
            __half h2 = __float2half_rn(p2), h3 = __float2half_rn(p3);
            __half2 t;
            t.x = h0; t.y = h1; pAh[nt] = *(uint32_t*)&t;
            t.x = h2; t.y = h3; pBh[nt] = *(uint32_t*)&t;
            t.x = __float2half_rn(p0 - __half2float(h0));
            t.y = __float2half_rn(p1 - __half2float(h1));
            pAl[nt] = *(uint32_t*)&t;
            t.x = __float2half_rn(p2 - __half2float(h2));
            t.y = __float2half_rn(p3 - __half2float(h3));
            pBl[nt] = *(uint32_t*)&t;
        }

        // ---- O += P . V (split; V via ldmatrix.trans from [kv][d]) ----
#pragma unroll
        for (int ks = 0; ks < 4; ks++) {
            uint32_t aPh[4] = { pAh[2 * ks], pBh[2 * ks], pAh[2 * ks + 1], pBh[2 * ks + 1] };
            uint32_t aPl[4] = { pAl[2 * ks], pBl[2 * ks], pAl[2 * ks + 1], pBl[2 * ks + 1] };
            uint32_t vh[8][2], vl[8][2];
#pragma unroll
            for (int ntd = 0; ntd < 8; ntd++) {
                uint32_t off = ((ks * 16 + (lane & 15)) * ST + ntd * 8) * 2;
                ldsm_x2_t(vh[ntd], uVh + off);
                ldsm_x2_t(vl[ntd], uVl + off);
            }
#pragma unroll
            for (int ntd = 0; ntd < 8; ntd++) mma16816(o[ntd], aPh, vh[ntd]);
#pragma unroll
            for (int ntd = 0; ntd < 8; ntd++) mma16816(o[ntd], aPl, vh[ntd]);
#pragma unroll
            for (int ntd = 0; ntd < 8; ntd++) mma16816(o[ntd], aPh, vl[ntd]);
        }
    }

    // ---- finalize: row-sum reduce, normalize, emit hi/lo concat layout ----
    lA += __shfl_xor_sync(0xffffffff, lA, 1);
    lA += __shfl_xor_sync(0xffffffff, lA, 2);
    lB += __shfl_xor_sync(0xffffffff, lB, 1);
    lB += __shfl_xor_sync(0xffffffff, lB, 2);
    float invA = 1.f / lA, invB = 1.f / lB;

    const int b = bh >> 4, h = bh & 15;
    const int rowA = q0 + w * 16 + (lane >> 2);
    const int rowB = rowA + 8;
    const int c2 = 2 * (lane & 3);
#pragma unroll
    for (int ntd = 0; ntd < 8; ntd++) {
        float v0 = o[ntd][0] * invA, v1 = o[ntd][1] * invA;
        float v2 = o[ntd][2] * invB, v3 = o[ntd][3] * invB;
        size_t offA = (size_t)(b * SEQ + rowA) * D_MODEL + h * D_K + ntd * 8 + c2;
        size_t offB = (size_t)(b * SEQ + rowB) * D_MODEL + h * D_K + ntd * 8 + c2;
        __half h0 = __float2half_rn(v0), h1 = __float2half_rn(v1);
        __half h2 = __float2half_rn(v2), h3 = __float2half_rn(v3);
        __half2 t;
        t.x = h0; t.y = h1; *(__half2*)&Oh[offA] = t;
        t.x = __float2half_rn(v0 - __half2float(h0));
        t.y = __float2half_rn(v1 - __half2float(h1));
        *(__half2*)&Ol[offA] = t;
        t.x = h2; t.y = h3; *(__half2*)&Oh[offB] = t;
        t.x = __float2half_rn(v2 - __half2float(h2));
        t.y = __float2half_rn(v3 - __half2float(h3));
        *(__half2*)&Ol[offB] = t;
    }
}

// ---------------------------------------------------------------------------
// Launch
// ---------------------------------------------------------------------------
extern "C" void kernel_launch(void* const* d_in, const int* in_sizes, int n_in,
                              void* d_out, int out_size)
{
    const float* q   = (const float*)d_in[0];
    const float* k   = (const float*)d_in[1];
    const float* v   = (const float*)d_in[2];
    const float* W_q = (const float*)d_in[3];
    const float* b_q = (const float*)d_in[4];
    const float* W_k = (const float*)d_in[5];
    const float* b_k = (const float*)d_in[6];
    const float* W_v = (const float*)d_in[7];
    const float* b_v = (const float*)d_in[8];
    const float* W_o = (const float*)d_in[9];
    const float* b_o = (const float*)d_in[10];
    float* out = (float*)d_out;

    __half* hf;
    cudaGetSymbolAddress((void**)&hf, g_hf);

    const int n4_act = M_TOK * D_MODEL / 4;
    const int n4_w   = D_MODEL * D_MODEL / 4;

    split_f16<<<n4_act / 256, 256>>>(q, hf + OFF_IQH, hf + OFF_IQL, n4_act);
    split_f16<<<n4_act / 256, 256>>>(k, hf + OFF_IKH, hf + OFF_IKL, n4_act);
    split_f16<<<n4_act / 256, 256>>>(v, hf + OFF_IVH, hf + OFF_IVL, n4_act);
    split_f16<<<n4_w / 256, 256>>>(W_q, hf + OFF_WQH, hf + OFF_WQL, n4_w);
    split_f16<<<n4_w / 256, 256>>>(W_k, hf + OFF_WKH, hf + OFF_WKL, n4_w);
    split_f16<<<n4_w / 256, 256>>>(W_v, hf + OFF_WVH, hf + OFF_WVL, n4_w);
    split_f16<<<n4_w / 256, 256>>>(W_o, hf + OFF_WOH, hf + OFF_WOL, n4_w);

    dim3 ggrid(D_MODEL / 128, M_TOK / 128);   // (8, 32)
    // Q projection pre-scaled by (1/sqrt(64)) * log2(e) for exp2-domain softmax
    const float qscale = 0.125f * 1.4426950408889634f;
    gemm_mma<1><<<ggrid, 256>>>(hf + OFF_IQH, hf + OFF_IQL,
                                hf + OFF_WQH, hf + OFF_WQL, b_q,
                                nullptr, hf + OFF_PQH, hf + OFF_PQL, qscale);
    gemm_mma<1><<<ggrid, 256>>>(hf + OFF_IKH, hf + OFF_IKL,
                                hf + OFF_WKH, hf + OFF_WKL, b_k,
                                nullptr, hf + OFF_PKH, hf + OFF_PKL, 1.0f);
    gemm_mma<1><<<ggrid, 256>>>(hf + OFF_IVH, hf + OFF_IVL,
                                hf + OFF_WVH, hf + OFF_WVL, b_v,
                                nullptr, hf + OFF_PVH, hf + OFF_PVL, 1.0f);

    dim3 agrid(SEQ / 64, BSZ * N_HEADS);      // (32, 32)
    flash_mma<<<agrid, 128>>>(hf + OFF_PQH, hf + OFF_PQL,
                              hf + OFF_PKH, hf + OFF_PKL,
                              hf + OFF_PVH, hf + OFF_PVL,
                              hf + OFF_OH, hf + OFF_OL);

    gemm_mma<0><<<ggrid, 256>>>(hf + OFF_OH, hf + OFF_OL,
                                hf + OFF_WOH, hf + OFF_WOL, b_o,
                                out, nullptr, nullptr, 1.0f);
}

// round 5
// speedup vs baseline: 3.5976x; 1.4052x over previous
#include <cuda_runtime.h>
#include <cuda_fp16.h>
#include <cstdint>

#define D_MODEL 1024
#define N_HEADS 16
#define D_K     64
#define SEQ     2048
#define BSZ     2
#define M_TOK   (BSZ * SEQ)   // 4096 tokens

// ---------------------------------------------------------------------------
// fp16 arena (device global: allocation-free rule). 64M halves = 128 MB.
// ---------------------------------------------------------------------------
#define MEG (1048576ULL)
__device__ __half g_hf[64 * MEG];

static const size_t OFF_IQH = 0,        OFF_IQL = 4 * MEG;
static const size_t OFF_IKH = 8 * MEG,  OFF_IKL = 12 * MEG;
static const size_t OFF_IVH = 16 * MEG, OFF_IVL = 20 * MEG;
static const size_t OFF_WQH = 24 * MEG, OFF_WQL = 25 * MEG;
static const size_t OFF_WKH = 26 * MEG, OFF_WKL = 27 * MEG;
static const size_t OFF_WVH = 28 * MEG, OFF_WVL = 29 * MEG;
static const size_t OFF_WOH = 30 * MEG, OFF_WOL = 31 * MEG;
static const size_t OFF_PQH = 32 * MEG, OFF_PQL = 36 * MEG;
static const size_t OFF_PKH = 40 * MEG, OFF_PKL = 44 * MEG;
static const size_t OFF_PVH = 48 * MEG, OFF_PVL = 52 * MEG;
static const size_t OFF_OH = 56 * MEG,  OFF_OL = 60 * MEG;

// ---------------------------------------------------------------------------
// PTX wrappers (baseline PTX — compiles at compute_103)
// ---------------------------------------------------------------------------
__device__ __forceinline__ uint32_t smem_u32(const void* p) {
    uint32_t a;
    asm("{ .reg .u64 t; cvta.to.shared.u64 t, %1; cvt.u32.u64 %0, t; }"
        : "=r"(a) : "l"(p));
    return a;
}
__device__ __forceinline__ void ldsm_x4(uint32_t* r, uint32_t addr) {
    asm volatile("ldmatrix.sync.aligned.m8n8.x4.shared.b16 {%0,%1,%2,%3}, [%4];"
                 : "=r"(r[0]), "=r"(r[1]), "=r"(r[2]), "=r"(r[3]) : "r"(addr));
}
__device__ __forceinline__ void ldsm_x2(uint32_t* r, uint32_t addr) {
    asm volatile("ldmatrix.sync.aligned.m8n8.x2.shared.b16 {%0,%1}, [%2];"
                 : "=r"(r[0]), "=r"(r[1]) : "r"(addr));
}
__device__ __forceinline__ void ldsm_x2_t(uint32_t* r, uint32_t addr) {
    asm volatile("ldmatrix.sync.aligned.m8n8.x2.trans.shared.b16 {%0,%1}, [%2];"
                 : "=r"(r[0]), "=r"(r[1]) : "r"(addr));
}
__device__ __forceinline__ void mma16816(float* d, const uint32_t* a, const uint32_t* b) {
    asm volatile(
        "mma.sync.aligned.m16n8k16.row.col.f32.f16.f16.f32 "
        "{%0,%1,%2,%3}, {%4,%5,%6,%7}, {%8,%9}, {%0,%1,%2,%3};"
        : "+f"(d[0]), "+f"(d[1]), "+f"(d[2]), "+f"(d[3])
        : "r"(a[0]), "r"(a[1]), "r"(a[2]), "r"(a[3]), "r"(b[0]), "r"(b[1]));
}
__device__ __forceinline__ void cp16(uint32_t saddr, const void* g) {
    asm volatile("cp.async.cg.shared.global [%0], [%1], 16;"
                 :: "r"(saddr), "l"(g));
}
#define CP_COMMIT() asm volatile("cp.async.commit_group;" ::: "memory")
#define CP_WAIT1()  asm volatile("cp.async.wait_group 1;" ::: "memory")
#define CP_WAIT0()  asm volatile("cp.async.wait_group 0;" ::: "memory")

// ---------------------------------------------------------------------------
// split: fp32 -> (hi fp16, lo fp16)
// ---------------------------------------------------------------------------
__global__ __launch_bounds__(256)
void split_f16(const float* __restrict__ x, __half* __restrict__ hi,
               __half* __restrict__ lo, int n4)
{
    int i = blockIdx.x * blockDim.x + threadIdx.x;
    if (i >= n4) return;
    float4 v = ((const float4*)x)[i];
    __half h0 = __float2half_rn(v.x), h1 = __float2half_rn(v.y);
    __half h2 = __float2half_rn(v.z), h3 = __float2half_rn(v.w);
    __half2 ph0; ph0.x = h0; ph0.y = h1;
    __half2 ph1; ph1.x = h2; ph1.y = h3;
    __half2 pl0; pl0.x = __float2half_rn(v.x - __half2float(h0));
    pl0.y = __float2half_rn(v.y - __half2float(h1));
    __half2 pl1; pl1.x = __float2half_rn(v.z - __half2float(h2));
    pl1.y = __float2half_rn(v.w - __half2float(h3));
    ((__half2*)hi)[i * 2 + 0] = ph0;
    ((__half2*)hi)[i * 2 + 1] = ph1;
    ((__half2*)lo)[i * 2 + 0] = pl0;
    ((__half2*)lo)[i * 2 + 1] = pl1;
}

// ---------------------------------------------------------------------------
// Tensor-core split-fp16 GEMM, 2-stage cp.async pipeline.
// MODE 0: fp32 output [m,n]. MODE 1: fp16 hi/lo output, [b,h,s,d] remap.
// CTA 128x128, BK=32, 256 threads, warp tile 64x32. Dynamic smem, 2 stages.
// ---------------------------------------------------------------------------
#define SP 40                       // smem row stride in halves (80B = 5x16B)
#define TSZB (128 * SP * 2)         // bytes per tile (10240)
#define STGB (4 * TSZB)             // bytes per stage (40960)
#define GSMEM (2 * STGB)            // 81920

template<int MODE>
__global__ __launch_bounds__(256)
void gemm_mma(const __half* __restrict__ Ahi, const __half* __restrict__ Alo,
              const __half* __restrict__ Bhi, const __half* __restrict__ Blo,
              const float* __restrict__ bias, float* __restrict__ C,
              __half* __restrict__ Ch, __half* __restrict__ Cl, float scale)
{
    extern __shared__ __align__(16) char dsm[];
    const uint32_t base = smem_u32(dsm);

    const int tid  = threadIdx.x;
    const int wid  = tid >> 5;
    const int lane = tid & 31;
    const int bm = blockIdx.y * 128;
    const int bn = blockIdx.x * 128;
    const int wm = (wid >> 2) * 64;
    const int wn = (wid & 3) * 32;

    // per-thread load coords (2 chunks of 16B per tile per iter)
    const int r0 = tid >> 1,            kc0 = (tid & 1) * 16;         // chunk j=0
    const int r1 = (tid + 256) >> 1,    kc1 = ((tid + 256) & 1) * 16; // same as r0+128? no:
    // simpler: chunk c = tid + j*256; row=c>>2; kcol=(c&3)*8
    float acc[4][4][4];
#pragma unroll
    for (int i = 0; i < 4; i++)
#pragma unroll
        for (int j = 0; j < 4; j++)
#pragma unroll
            for (int r = 0; r < 4; r++) acc[i][j][r] = 0.f;

    const int arow = lane & 15;
    const int acol = (lane >> 4) * 8;
    const int brow = lane & 7;
    const int bcol = ((lane & 15) >> 3) * 8;

    auto load_stage = [&](int stg, int k0) {
        uint32_t sb = base + stg * STGB;
#pragma unroll
        for (int j = 0; j < 2; j++) {
            int c    = tid + j * 256;
            int row  = c >> 2;
            int kcol = (c & 3) * 8;
            size_t ga = (size_t)(bm + row) * D_MODEL + k0 + kcol;
            size_t gb = (size_t)(bn + row) * D_MODEL + k0 + kcol;
            uint32_t so = (uint32_t)(row * SP + kcol) * 2;
            cp16(sb + 0 * TSZB + so, &Ahi[ga]);
            cp16(sb + 1 * TSZB + so, &Alo[ga]);
            cp16(sb + 2 * TSZB + so, &Bhi[gb]);
            cp16(sb + 3 * TSZB + so, &Blo[gb]);
        }
    };

    load_stage(0, 0);
    CP_COMMIT();

    for (int kc = 0; kc < 32; kc++) {
        const int cur = kc & 1;
        if (kc < 31) {
            load_stage(cur ^ 1, (kc + 1) * 32);
            CP_COMMIT();
            CP_WAIT1();
        } else {
            CP_WAIT0();
        }
        __syncthreads();

        const uint32_t uAh = base + cur * STGB;
        const uint32_t uAl = uAh + TSZB;
        const uint32_t uBh = uAh + 2 * TSZB;
        const uint32_t uBl = uAh + 3 * TSZB;

#pragma unroll
        for (int ks = 0; ks < 2; ks++) {
            uint32_t ah[4][4], al[4][4];
#pragma unroll
            for (int mt = 0; mt < 4; mt++) {
                uint32_t off = ((wm + mt * 16 + arow) * SP + ks * 16 + acol) * 2;
                ldsm_x4(ah[mt], uAh + off);
                ldsm_x4(al[mt], uAl + off);
            }
            uint32_t bh[4][2];
#pragma unroll
            for (int nt = 0; nt < 4; nt++) {
                uint32_t off = ((wn + nt * 8 + brow) * SP + ks * 16 + bcol) * 2;
                ldsm_x2(bh[nt], uBh + off);
            }
#pragma unroll
            for (int mt = 0; mt < 4; mt++)
#pragma unroll
                for (int nt = 0; nt < 4; nt++) {
                    mma16816(acc[mt][nt], ah[mt], bh[nt]);
                    mma16816(acc[mt][nt], al[mt], bh[nt]);
                }
            uint32_t bl[4][2];
#pragma unroll
            for (int nt = 0; nt < 4; nt++) {
                uint32_t off = ((wn + nt * 8 + brow) * SP + ks * 16 + bcol) * 2;
                ldsm_x2(bl[nt], uBl + off);
            }
#pragma unroll
            for (int mt = 0; mt < 4; mt++)
#pragma unroll
                for (int nt = 0; nt < 4; nt++)
                    mma16816(acc[mt][nt], ah[mt], bl[nt]);
        }
        __syncthreads();
    }

#pragma unroll
    for (int mt = 0; mt < 4; mt++) {
#pragma unroll
        for (int half = 0; half < 2; half++) {
            int m = bm + wm + mt * 16 + (lane >> 2) + half * 8;
            int b = m >> 11, s = m & 2047;
#pragma unroll
            for (int nt = 0; nt < 4; nt++) {
                int n = bn + wn + nt * 8 + 2 * (lane & 3);
                float vx = (acc[mt][nt][half * 2 + 0] + bias[n + 0]) * scale;
                float vy = (acc[mt][nt][half * 2 + 1] + bias[n + 1]) * scale;
                if (MODE == 1) {
                    int h = n >> 6, dd = n & 63;
                    size_t co = ((size_t)(b * N_HEADS + h) * SEQ + s) * D_K + dd;
                    __half hx = __float2half_rn(vx), hy = __float2half_rn(vy);
                    __half2 hh; hh.x = hx; hh.y = hy;
                    __half2 ll;
                    ll.x = __float2half_rn(vx - __half2float(hx));
                    ll.y = __float2half_rn(vy - __half2float(hy));
                    *(__half2*)&Ch[co] = hh;
                    *(__half2*)&Cl[co] = ll;
                } else {
                    float2 v; v.x = vx; v.y = vy;
                    *(float2*)&C[(size_t)m * D_MODEL + n] = v;
                }
            }
        }
    }
}

// ---------------------------------------------------------------------------
// Flash attention, mma.sync fp16-split, 2-stage cp.async KV pipeline.
// Block = 128 threads (4 warps), 64 q-rows per CTA, KV tiles 64.
// ---------------------------------------------------------------------------
#define ST 72                        // kv smem row stride in halves (144B = 9x16B)
#define FTSZB (64 * ST * 2)          // bytes per kv tile (9216)
#define FSTGB (4 * FTSZB)            // bytes per stage (36864)
#define FSMEM (2 * FSTGB)            // 73728

__global__ __launch_bounds__(128)
void flash_mma(const __half* __restrict__ Qh, const __half* __restrict__ Ql,
               const __half* __restrict__ Kh, const __half* __restrict__ Kl,
               const __half* __restrict__ Vh, const __half* __restrict__ Vl,
               __half* __restrict__ Oh, __half* __restrict__ Ol)
{
    extern __shared__ __align__(16) char fsm[];
    const uint32_t base = smem_u32(fsm);

    const int bh  = blockIdx.y;
    const int q0  = blockIdx.x * 64;
    const int tid = threadIdx.x;
    const int w   = tid >> 5;
    const int lane = tid & 31;
    const size_t bhoff = (size_t)bh * SEQ * D_K;

    // ---- stage Q in buffer 1 (Kh/Kl slots), extract A-fragments ----
    {
        __half* sQh = (__half*)(fsm + FSTGB);
        __half* sQl = (__half*)(fsm + FSTGB + FTSZB);
#pragma unroll
        for (int it = 0; it < 4; it++) {
            int idx = tid + it * 128;
            int row = idx >> 3, c8 = (idx & 7) * 8;
            size_t g = bhoff + (size_t)(q0 + row) * D_K + c8;
            *(uint4*)&sQh[row * ST + c8] = *(const uint4*)&Qh[g];
            *(uint4*)&sQl[row * ST + c8] = *(const uint4*)&Ql[g];
        }
    }
    __syncthreads();
    uint32_t qh[4][4], ql[4][4];
    {
        const uint32_t uQh = base + FSTGB, uQl = base + FSTGB + FTSZB;
        const int arow = lane & 15, acol = (lane >> 4) * 8;
#pragma unroll
        for (int ks = 0; ks < 4; ks++) {
            uint32_t off = ((w * 16 + arow) * ST + ks * 16 + acol) * 2;
            ldsm_x4(qh[ks], uQh + off);
            ldsm_x4(ql[ks], uQl + off);
        }
    }
    __syncthreads();   // all frag reads done before buffer 1 is reused

    auto load_kv = [&](int stg, int kv0) {
        uint32_t sb = base + stg * FSTGB;
#pragma unroll
        for (int it = 0; it < 4; it++) {
            int idx = tid + it * 128;
            int row = idx >> 3, c8 = (idx & 7) * 8;
            size_t g = bhoff + (size_t)(kv0 + row) * D_K + c8;
            uint32_t so = (uint32_t)(row * ST + c8) * 2;
            cp16(sb + 0 * FTSZB + so, &Kh[g]);
            cp16(sb + 1 * FTSZB + so, &Kl[g]);
            cp16(sb + 2 * FTSZB + so, &Vh[g]);
            cp16(sb + 3 * FTSZB + so, &Vl[g]);
        }
    };

    float o[8][4];
#pragma unroll
    for (int i = 0; i < 8; i++)
#pragma unroll
        for (int r = 0; r < 4; r++) o[i][r] = 0.f;
    float mA = -1e30f, mB = -1e30f, lA = 0.f, lB = 0.f;

    load_kv(0, 0);
    CP_COMMIT();

    for (int t = 0; t < SEQ / 64; t++) {
        const int cur = t & 1;
        if (t < SEQ / 64 - 1) {
            load_kv(cur ^ 1, (t + 1) * 64);
            CP_COMMIT();
            CP_WAIT1();
        } else {
            CP_WAIT0();
        }
        __syncthreads();

        const uint32_t uKh = base + cur * FSTGB;
        const uint32_t uKl = uKh + FTSZB;
        const uint32_t uVh = uKh + 2 * FTSZB;
        const uint32_t uVl = uKh + 3 * FTSZB;

        // ---- S = Q . K^T ----
        float s[8][4];
#pragma unroll
        for (int i = 0; i < 8; i++)
#pragma unroll
            for (int r = 0; r < 4; r++) s[i][r] = 0.f;

        const int brow = lane & 7;
        const int bcol = ((lane & 15) >> 3) * 8;
#pragma unroll
        for (int ks = 0; ks < 4; ks++) {
            uint32_t kh[8][2], kl[8][2];
#pragma unroll
            for (int nt = 0; nt < 8; nt++) {
                uint32_t off = ((nt * 8 + brow) * ST + ks * 16 + bcol) * 2;
                ldsm_x2(kh[nt], uKh + off);
                ldsm_x2(kl[nt], uKl + off);
            }
#pragma unroll
            for (int nt = 0; nt < 8; nt++) mma16816(s[nt], qh[ks], kh[nt]);
#pragma unroll
            for (int nt = 0; nt < 8; nt++) mma16816(s[nt], ql[ks], kh[nt]);
#pragma unroll
            for (int nt = 0; nt < 8; nt++) mma16816(s[nt], qh[ks], kl[nt]);
        }

        // ---- online softmax (log2 domain) ----
        float tA = -1e30f, tB = -1e30f;
#pragma unroll
        for (int nt = 0; nt < 8; nt++) {
            tA = fmaxf(tA, fmaxf(s[nt][0], s[nt][1]));
            tB = fmaxf(tB, fmaxf(s[nt][2], s[nt][3]));
        }
        tA = fmaxf(tA, __shfl_xor_sync(0xffffffff, tA, 1));
        tA = fmaxf(tA, __shfl_xor_sync(0xffffffff, tA, 2));
        tB = fmaxf(tB, __shfl_xor_sync(0xffffffff, tB, 1));
        tB = fmaxf(tB, __shfl_xor_sync(0xffffffff, tB, 2));
        float mnA = fmaxf(mA, tA), mnB = fmaxf(mB, tB);
        float cA = exp2f(mA - mnA), cB = exp2f(mB - mnB);
        lA *= cA; lB *= cB;
#pragma unroll
        for (int nt = 0; nt < 8; nt++) {
            o[nt][0] *= cA; o[nt][1] *= cA;
            o[nt][2] *= cB; o[nt][3] *= cB;
        }
        mA = mnA; mB = mnB;

        // ---- P = exp2(S - m), split hi/lo in registers ----
        uint32_t pAh[8], pAl[8], pBh[8], pBl[8];
#pragma unroll
        for (int nt = 0; nt < 8; nt++) {
            float p0 = exp2f(s[nt][0] - mnA);
            float p1 = exp2f(s[nt][1] - mnA);
            float p2 = exp2f(s[nt][2] - mnB);
            float p3 = exp2f(s[nt][3] - mnB);
            lA += p0 + p1; lB += p2 + p3;
            __half h0 = __float2half_rn(p0), h1 = __float2half_rn(p1);
            __half h2 = __float2half_rn(p2), h3 = __float2half_rn(p3);
            __half2 tt;
            tt.x = h0; tt.y = h1; pAh[nt] = *(uint32_t*)&tt;
            tt.x = h2; tt.y = h3; pBh[nt] = *(uint32_t*)&tt;
            tt.x = __float2half_rn(p0 - __half2float(h0));
            tt.y = __float2half_rn(p1 - __half2float(h1));
            pAl[nt] = *(uint32_t*)&tt;
            tt.x = __float2half_rn(p2 - __half2float(h2));
            tt.y = __float2half_rn(p3 - __half2float(h3));
            pBl[nt] = *(uint32_t*)&tt;
        }

        // ---- O += P . V ----
#pragma unroll
        for (int ks = 0; ks < 4; ks++) {
            uint32_t aPh[4] = { pAh[2 * ks], pBh[2 * ks], pAh[2 * ks + 1], pBh[2 * ks + 1] };
            uint32_t aPl[4] = { pAl[2 * ks], pBl[2 * ks], pAl[2 * ks + 1], pBl[2 * ks + 1] };
            uint32_t vh[8][2], vl[8][2];
#pragma unroll
            for (int ntd = 0; ntd < 8; ntd++) {
                uint32_t off = ((ks * 16 + (lane & 15)) * ST + ntd * 8) * 2;
                ldsm_x2_t(vh[ntd], uVh + off);
                ldsm_x2_t(vl[ntd], uVl + off);
            }
#pragma unroll
            for (int ntd = 0; ntd < 8; ntd++) mma16816(o[ntd], aPh, vh[ntd]);
#pragma unroll
            for (int ntd = 0; ntd < 8; ntd++) mma16816(o[ntd], aPl, vh[ntd]);
#pragma unroll
            for (int ntd = 0; ntd < 8; ntd++) mma16816(o[ntd], aPh, vl[ntd]);
        }
        __syncthreads();
    }

    // ---- finalize ----
    lA += __shfl_xor_sync(0xffffffff, lA, 1);
    lA += __shfl_xor_sync(0xffffffff, lA, 2);
    lB += __shfl_xor_sync(0xffffffff, lB, 1);
    lB += __shfl_xor_sync(0xffffffff, lB, 2);
    float invA = 1.f / lA, invB = 1.f / lB;

    const int b = bh >> 4, h = bh & 15;
    const int rowA = q0 + w * 16 + (lane >> 2);
    const int rowB = rowA + 8;
    const int c2 = 2 * (lane & 3);
#pragma unroll
    for (int ntd = 0; ntd < 8; ntd++) {
        float v0 = o[ntd][0] * invA, v1 = o[ntd][1] * invA;
        float v2 = o[ntd][2] * invB, v3 = o[ntd][3] * invB;
        size_t offA = (size_t)(b * SEQ + rowA) * D_MODEL + h * D_K + ntd * 8 + c2;
        size_t offB = (size_t)(b * SEQ + rowB) * D_MODEL + h * D_K + ntd * 8 + c2;
        __half h0 = __float2half_rn(v0), h1 = __float2half_rn(v1);
        __half h2 = __float2half_rn(v2), h3 = __float2half_rn(v3);
        __half2 t;
        t.x = h0; t.y = h1; *(__half2*)&Oh[offA] = t;
        t.x = __float2half_rn(v0 - __half2float(h0));
        t.y = __float2half_rn(v1 - __half2float(h1));
        *(__half2*)&Ol[offA] = t;
        t.x = h2; t.y = h3; *(__half2*)&Oh[offB] = t;
        t.x = __float2half_rn(v2 - __half2float(h2));
        t.y = __float2half_rn(v3 - __half2float(h3));
        *(__half2*)&Ol[offB] = t;
    }
}

// ---------------------------------------------------------------------------
// Launch
// ---------------------------------------------------------------------------
extern "C" void kernel_launch(void* const* d_in, const int* in_sizes, int n_in,
                              void* d_out, int out_size)
{
    const float* q   = (const float*)d_in[0];
    const float* k   = (const float*)d_in[1];
    const float* v   = (const float*)d_in[2];
    const float* W_q = (const float*)d_in[3];
    const float* b_q = (const float*)d_in[4];
    const float* W_k = (const float*)d_in[5];
    const float* b_k = (const float*)d_in[6];
    const float* W_v = (const float*)d_in[7];
    const float* b_v = (const float*)d_in[8];
    const float* W_o = (const float*)d_in[9];
    const float* b_o = (const float*)d_in[10];
    float* out = (float*)d_out;

    __half* hf;
    cudaGetSymbolAddress((void**)&hf, g_hf);

    cudaFuncSetAttribute((void*)gemm_mma<0>, cudaFuncAttributeMaxDynamicSharedMemorySize, GSMEM);
    cudaFuncSetAttribute((void*)gemm_mma<1>, cudaFuncAttributeMaxDynamicSharedMemorySize, GSMEM);
    cudaFuncSetAttribute((void*)flash_mma, cudaFuncAttributeMaxDynamicSharedMemorySize, FSMEM);

    const int n4_act = M_TOK * D_MODEL / 4;
    const int n4_w   = D_MODEL * D_MODEL / 4;

    split_f16<<<n4_act / 256, 256>>>(q, hf + OFF_IQH, hf + OFF_IQL, n4_act);
    split_f16<<<n4_act / 256, 256>>>(k, hf + OFF_IKH, hf + OFF_IKL, n4_act);
    split_f16<<<n4_act / 256, 256>>>(v, hf + OFF_IVH, hf + OFF_IVL, n4_act);
    split_f16<<<n4_w / 256, 256>>>(W_q, hf + OFF_WQH, hf + OFF_WQL, n4_w);
    split_f16<<<n4_w / 256, 256>>>(W_k, hf + OFF_WKH, hf + OFF_WKL, n4_w);
    split_f16<<<n4_w / 256, 256>>>(W_v, hf + OFF_WVH, hf + OFF_WVL, n4_w);
    split_f16<<<n4_w / 256, 256>>>(W_o, hf + OFF_WOH, hf + OFF_WOL, n4_w);

    dim3 ggrid(D_MODEL / 128, M_TOK / 128);   // (8, 32)
    const float qscale = 0.125f * 1.4426950408889634f;
    gemm_mma<1><<<ggrid, 256, GSMEM>>>(hf + OFF_IQH, hf + OFF_IQL,
                                       hf + OFF_WQH, hf + OFF_WQL, b_q,
                                       nullptr, hf + OFF_PQH, hf + OFF_PQL, qscale);
    gemm_mma<1><<<ggrid, 256, GSMEM>>>(hf + OFF_IKH, hf + OFF_IKL,
                                       hf + OFF_WKH, hf + OFF_WKL, b_k,
                                       nullptr, hf + OFF_PKH, hf + OFF_PKL, 1.0f);
    gemm_mma<1><<<ggrid, 256, GSMEM>>>(hf + OFF_IVH, hf + OFF_IVL,
                                       hf + OFF_WVH, hf + OFF_WVL, b_v,
                                       nullptr, hf + OFF_PVH, hf + OFF_PVL, 1.0f);

    dim3 agrid(SEQ / 64, BSZ * N_HEADS);      // (32, 32)
    flash_mma<<<agrid, 128, FSMEM>>>(hf + OFF_PQH, hf + OFF_PQL,
                                     hf + OFF_PKH, hf + OFF_PKL,
                                     hf + OFF_PVH, hf + OFF_PVL,
                                     hf + OFF_OH, hf + OFF_OL);

    gemm_mma<0><<<ggrid, 256, GSMEM>>>(hf + OFF_OH, hf + OFF_OL,
                                       hf + OFF_WOH, hf + OFF_WOL, b_o,
                                       out, nullptr, nullptr, 1.0f);
}

// round 6
// speedup vs baseline: 3.7680x; 1.0474x over previous
#include <cuda_runtime.h>
#include <cuda_fp16.h>
#include <cstdint>

#define D_MODEL 1024
#define N_HEADS 16
#define D_K     64
#define SEQ     2048
#define BSZ     2
#define M_TOK   (BSZ * SEQ)   // 4096 tokens

// ---------------------------------------------------------------------------
// fp16 arena (device global: allocation-free rule). 64M halves = 128 MB.
// ---------------------------------------------------------------------------
#define MEG (1048576ULL)
__device__ __half g_hf[64 * MEG];

static const size_t OFF_IQH = 0,        OFF_IQL = 4 * MEG;
static const size_t OFF_IKH = 8 * MEG,  OFF_IKL = 12 * MEG;
static const size_t OFF_IVH = 16 * MEG, OFF_IVL = 20 * MEG;
static const size_t OFF_WQH = 24 * MEG, OFF_WQL = 25 * MEG;
static const size_t OFF_WKH = 26 * MEG, OFF_WKL = 27 * MEG;
static const size_t OFF_WVH = 28 * MEG, OFF_WVL = 29 * MEG;
static const size_t OFF_WOH = 30 * MEG, OFF_WOL = 31 * MEG;
static const size_t OFF_PQH = 32 * MEG, OFF_PQL = 36 * MEG;
static const size_t OFF_PKH = 40 * MEG, OFF_PKL = 44 * MEG;
static const size_t OFF_PVH = 48 * MEG, OFF_PVL = 52 * MEG;
static const size_t OFF_OH = 56 * MEG,  OFF_OL = 60 * MEG;

// ---------------------------------------------------------------------------
// PTX wrappers (baseline PTX — compiles at compute_103)
// ---------------------------------------------------------------------------
__device__ __forceinline__ uint32_t smem_u32(const void* p) {
    uint32_t a;
    asm("{ .reg .u64 t; cvta.to.shared.u64 t, %1; cvt.u32.u64 %0, t; }"
        : "=r"(a) : "l"(p));
    return a;
}
__device__ __forceinline__ void ldsm_x4(uint32_t* r, uint32_t addr) {
    asm volatile("ldmatrix.sync.aligned.m8n8.x4.shared.b16 {%0,%1,%2,%3}, [%4];"
                 : "=r"(r[0]), "=r"(r[1]), "=r"(r[2]), "=r"(r[3]) : "r"(addr));
}
__device__ __forceinline__ void ldsm_x2(uint32_t* r, uint32_t addr) {
    asm volatile("ldmatrix.sync.aligned.m8n8.x2.shared.b16 {%0,%1}, [%2];"
                 : "=r"(r[0]), "=r"(r[1]) : "r"(addr));
}
__device__ __forceinline__ void ldsm_x2_t(uint32_t* r, uint32_t addr) {
    asm volatile("ldmatrix.sync.aligned.m8n8.x2.trans.shared.b16 {%0,%1}, [%2];"
                 : "=r"(r[0]), "=r"(r[1]) : "r"(addr));
}
__device__ __forceinline__ void mma16816(float* d, const uint32_t* a, const uint32_t* b) {
    asm volatile(
        "mma.sync.aligned.m16n8k16.row.col.f32.f16.f16.f32 "
        "{%0,%1,%2,%3}, {%4,%5,%6,%7}, {%8,%9}, {%0,%1,%2,%3};"
        : "+f"(d[0]), "+f"(d[1]), "+f"(d[2]), "+f"(d[3])
        : "r"(a[0]), "r"(a[1]), "r"(a[2]), "r"(a[3]), "r"(b[0]), "r"(b[1]));
}
__device__ __forceinline__ void cp16(uint32_t saddr, const void* g) {
    asm volatile("cp.async.cg.shared.global [%0], [%1], 16;"
                 :: "r"(saddr), "l"(g));
}
#define CP_COMMIT() asm volatile("cp.async.commit_group;" ::: "memory")
#define CP_WAIT0()  asm volatile("cp.async.wait_group 0;" ::: "memory")

// ---------------------------------------------------------------------------
// Fused split: all 7 tensors (q,k,v acts + 4 weights) in ONE launch.
// Segment sizes (in 256-thread float4 blocks): 3 x 4096 (acts), 4 x 1024 (w).
// ---------------------------------------------------------------------------
struct SplitArgs {
    const float* src[7];
    __half* hi[7];
    __half* lo[7];
};

__global__ __launch_bounds__(256)
void split_all(SplitArgs a)
{
    int blk = blockIdx.x;
    int seg, rel;
    if (blk < 12288) { seg = blk >> 12; rel = blk & 4095; }          // acts
    else             { seg = 3 + ((blk - 12288) >> 10); rel = (blk - 12288) & 1023; }
    int i = rel * 256 + threadIdx.x;

    float4 v = ((const float4*)a.src[seg])[i];
    __half h0 = __float2half_rn(v.x), h1 = __float2half_rn(v.y);
    __half h2 = __float2half_rn(v.z), h3 = __float2half_rn(v.w);
    __half2 ph0; ph0.x = h0; ph0.y = h1;
    __half2 ph1; ph1.x = h2; ph1.y = h3;
    __half2 pl0; pl0.x = __float2half_rn(v.x - __half2float(h0));
    pl0.y = __float2half_rn(v.y - __half2float(h1));
    __half2 pl1; pl1.x = __float2half_rn(v.z - __half2float(h2));
    pl1.y = __float2half_rn(v.w - __half2float(h3));
    ((__half2*)a.hi[seg])[i * 2 + 0] = ph0;
    ((__half2*)a.hi[seg])[i * 2 + 1] = ph1;
    ((__half2*)a.lo[seg])[i * 2 + 0] = pl0;
    ((__half2*)a.lo[seg])[i * 2 + 1] = pl1;
}

// ---------------------------------------------------------------------------
// Tensor-core split-fp16 GEMM core (2-stage cp.async, single sync per iter).
// CTA 128x128, BK=32, 256 threads, warp tile 64x32.
// ---------------------------------------------------------------------------
#define SP 40                       // smem row stride in halves (80B = 5x16B)
#define TSZB (128 * SP * 2)         // bytes per tile (10240)
#define STGB (4 * TSZB)             // bytes per stage (40960)
#define GSMEM (2 * STGB)            // 81920

struct GemmOne {
    const __half* Ah; const __half* Al;
    const __half* Bh; const __half* Bl;
    const float* bias;
    __half* Ch; __half* Cl;      // MODE 1 outputs
    float* C;                    // MODE 0 output
    float scale;
};
struct GemmQKV { GemmOne g[3]; };

template<int MODE>
__device__ __forceinline__ void gemm_core(const GemmOne& P, int bm, int bn)
{
    extern __shared__ __align__(16) char dsm[];
    const uint32_t base = smem_u32(dsm);
    const int tid  = threadIdx.x;
    const int wid  = tid >> 5;
    const int lane = tid & 31;
    const int wm = (wid >> 2) * 64;
    const int wn = (wid & 3) * 32;

    float acc[4][4][4];
#pragma unroll
    for (int i = 0; i < 4; i++)
#pragma unroll
        for (int j = 0; j < 4; j++)
#pragma unroll
            for (int r = 0; r < 4; r++) acc[i][j][r] = 0.f;

    const int arow = lane & 15;
    const int acol = (lane >> 4) * 8;
    const int brow = lane & 7;
    const int bcol = ((lane & 15) >> 3) * 8;

    auto load_stage = [&](int stg, int k0) {
        uint32_t sb = base + stg * STGB;
#pragma unroll
        for (int j = 0; j < 2; j++) {
            int c    = tid + j * 256;
            int row  = c >> 2;
            int kcol = (c & 3) * 8;
            size_t ga = (size_t)(bm + row) * D_MODEL + k0 + kcol;
            size_t gb = (size_t)(bn + row) * D_MODEL + k0 + kcol;
            uint32_t so = (uint32_t)(row * SP + kcol) * 2;
            cp16(sb + 0 * TSZB + so, &P.Ah[ga]);
            cp16(sb + 1 * TSZB + so, &P.Al[ga]);
            cp16(sb + 2 * TSZB + so, &P.Bh[gb]);
            cp16(sb + 3 * TSZB + so, &P.Bl[gb]);
        }
    };

    load_stage(0, 0);
    CP_COMMIT();

    for (int kc = 0; kc < 32; kc++) {
        const int cur = kc & 1;
        CP_WAIT0();            // all committed groups done -> stage cur ready
        __syncthreads();       // also: everyone finished reading buffer cur^1
        if (kc < 31) {
            load_stage(cur ^ 1, (kc + 1) * 32);
            CP_COMMIT();
        }

        const uint32_t uAh = base + cur * STGB;
        const uint32_t uAl = uAh + TSZB;
        const uint32_t uBh = uAh + 2 * TSZB;
        const uint32_t uBl = uAh + 3 * TSZB;

#pragma unroll
        for (int ks = 0; ks < 2; ks++) {
            uint32_t ah[4][4], al[4][4];
#pragma unroll
            for (int mt = 0; mt < 4; mt++) {
                uint32_t off = ((wm + mt * 16 + arow) * SP + ks * 16 + acol) * 2;
                ldsm_x4(ah[mt], uAh + off);
                ldsm_x4(al[mt], uAl + off);
            }
            uint32_t bh[4][2];
#pragma unroll
            for (int nt = 0; nt < 4; nt++) {
                uint32_t off = ((wn + nt * 8 + brow) * SP + ks * 16 + bcol) * 2;
                ldsm_x2(bh[nt], uBh + off);
            }
#pragma unroll
            for (int mt = 0; mt < 4; mt++)
#pragma unroll
                for (int nt = 0; nt < 4; nt++) {
                    mma16816(acc[mt][nt], ah[mt], bh[nt]);
                    mma16816(acc[mt][nt], al[mt], bh[nt]);
                }
            uint32_t bl[4][2];
#pragma unroll
            for (int nt = 0; nt < 4; nt++) {
                uint32_t off = ((wn + nt * 8 + brow) * SP + ks * 16 + bcol) * 2;
                ldsm_x2(bl[nt], uBl + off);
            }
#pragma unroll
            for (int mt = 0; mt < 4; mt++)
#pragma unroll
                for (int nt = 0; nt < 4; nt++)
                    mma16816(acc[mt][nt], ah[mt], bl[nt]);
        }
    }

#pragma unroll
    for (int mt = 0; mt < 4; mt++) {
#pragma unroll
        for (int half = 0; half < 2; half++) {
            int m = bm + wm + mt * 16 + (lane >> 2) + half * 8;
            int b = m >> 11, s = m & 2047;
#pragma unroll
            for (int nt = 0; nt < 4; nt++) {
                int n = bn + wn + nt * 8 + 2 * (lane & 3);
                float vx = (acc[mt][nt][half * 2 + 0] + P.bias[n + 0]) * P.scale;
                float vy = (acc[mt][nt][half * 2 + 1] + P.bias[n + 1]) * P.scale;
                if (MODE == 1) {
                    int h = n >> 6, dd = n & 63;
                    size_t co = ((size_t)(b * N_HEADS + h) * SEQ + s) * D_K + dd;
                    __half hx = __float2half_rn(vx), hy = __float2half_rn(vy);
                    __half2 hh; hh.x = hx; hh.y = hy;
                    __half2 ll;
                    ll.x = __float2half_rn(vx - __half2float(hx));
                    ll.y = __float2half_rn(vy - __half2float(hy));
                    *(__half2*)&P.Ch[co] = hh;
                    *(__half2*)&P.Cl[co] = ll;
                } else {
                    float2 v; v.x = vx; v.y = vy;
                    *(float2*)&P.C[(size_t)m * D_MODEL + n] = v;
                }
            }
        }
    }
}

// Fused Q/K/V projection GEMMs: blockIdx.z selects the GEMM.
__global__ __launch_bounds__(256)
void gemm_qkv(GemmQKV P)
{
    gemm_core<1>(P.g[blockIdx.z], blockIdx.y * 128, blockIdx.x * 128);
}

// Output projection GEMM (fp32 out).
__global__ __launch_bounds__(256)
void gemm_o(GemmOne P)
{
    gemm_core<0>(P, blockIdx.y * 128, blockIdx.x * 128);
}

// ---------------------------------------------------------------------------
// Flash attention, mma.sync fp16-split, 2-stage cp.async, single sync/iter.
// Block = 128 threads (4 warps), 64 q-rows per CTA, KV tiles 64.
// ---------------------------------------------------------------------------
#define ST 72                        // kv smem row stride in halves (144B)
#define FTSZB (64 * ST * 2)          // bytes per kv tile (9216)
#define FSTGB (4 * FTSZB)            // bytes per stage (36864)
#define FSMEM (2 * FSTGB)            // 73728

__global__ __launch_bounds__(128)
void flash_mma(const __half* __restrict__ Qh, const __half* __restrict__ Ql,
               const __half* __restrict__ Kh, const __half* __restrict__ Kl,
               const __half* __restrict__ Vh, const __half* __restrict__ Vl,
               __half* __restrict__ Oh, __half* __restrict__ Ol)
{
    extern __shared__ __align__(16) char fsm[];
    const uint32_t base = smem_u32(fsm);

    const int bh  = blockIdx.y;
    const int q0  = blockIdx.x * 64;
    const int tid = threadIdx.x;
    const int w   = tid >> 5;
    const int lane = tid & 31;
    const size_t bhoff = (size_t)bh * SEQ * D_K;

    // ---- stage Q in buffer 1, extract A-fragments ----
    {
        __half* sQh = (__half*)(fsm + FSTGB);
        __half* sQl = (__half*)(fsm + FSTGB + FTSZB);
#pragma unroll
        for (int it = 0; it < 4; it++) {
            int idx = tid + it * 128;
            int row = idx >> 3, c8 = (idx & 7) * 8;
            size_t g = bhoff + (size_t)(q0 + row) * D_K + c8;
            *(uint4*)&sQh[row * ST + c8] = *(const uint4*)&Qh[g];
            *(uint4*)&sQl[row * ST + c8] = *(const uint4*)&Ql[g];
        }
    }
    __syncthreads();
    uint32_t qh[4][4], ql[4][4];
    {
        const uint32_t uQh = base + FSTGB, uQl = base + FSTGB + FTSZB;
        const int arow = lane & 15, acol = (lane >> 4) * 8;
#pragma unroll
        for (int ks = 0; ks < 4; ks++) {
            uint32_t off = ((w * 16 + arow) * ST + ks * 16 + acol) * 2;
            ldsm_x4(qh[ks], uQh + off);
            ldsm_x4(ql[ks], uQl + off);
        }
    }
    __syncthreads();   // frag reads done before buffer 1 is reused

    auto load_kv = [&](int stg, int kv0) {
        uint32_t sb = base + stg * FSTGB;
#pragma unroll
        for (int it = 0; it < 4; it++) {
            int idx = tid + it * 128;
            int row = idx >> 3, c8 = (idx & 7) * 8;
            size_t g = bhoff + (size_t)(kv0 + row) * D_K + c8;
            uint32_t so = (uint32_t)(row * ST + c8) * 2;
            cp16(sb + 0 * FTSZB + so, &Kh[g]);
            cp16(sb + 1 * FTSZB + so, &Kl[g]);
            cp16(sb + 2 * FTSZB + so, &Vh[g]);
            cp16(sb + 3 * FTSZB + so, &Vl[g]);
        }
    };

    float o[8][4];
#pragma unroll
    for (int i = 0; i < 8; i++)
#pragma unroll
        for (int r = 0; r < 4; r++) o[i][r] = 0.f;
    float mA = -1e30f, mB = -1e30f, lA = 0.f, lB = 0.f;

    load_kv(0, 0);
    CP_COMMIT();

    for (int t = 0; t < SEQ / 64; t++) {
        const int cur = t & 1;
        CP_WAIT0();
        __syncthreads();
        if (t < SEQ / 64 - 1) {
            load_kv(cur ^ 1, (t + 1) * 64);
            CP_COMMIT();
        }

        const uint32_t uKh = base + cur * FSTGB;
        const uint32_t uKl = uKh + FTSZB;
        const uint32_t uVh = uKh + 2 * FTSZB;
        const uint32_t uVl = uKh + 3 * FTSZB;

        // ---- S = Q . K^T ----
        float s[8][4];
#pragma unroll
        for (int i = 0; i < 8; i++)
#pragma unroll
            for (int r = 0; r < 4; r++) s[i][r] = 0.f;

        const int brow = lane & 7;
        const int bcol = ((lane & 15) >> 3) * 8;
#pragma unroll
        for (int ks = 0; ks < 4; ks++) {
            uint32_t kh[8][2], kl[8][2];
#pragma unroll
            for (int nt = 0; nt < 8; nt++) {
                uint32_t off = ((nt * 8 + brow) * ST + ks * 16 + bcol) * 2;
                ldsm_x2(kh[nt], uKh + off);
                ldsm_x2(kl[nt], uKl + off);
            }
#pragma unroll
            for (int nt = 0; nt < 8; nt++) mma16816(s[nt], qh[ks], kh[nt]);
#pragma unroll
            for (int nt = 0; nt < 8; nt++) mma16816(s[nt], ql[ks], kh[nt]);
#pragma unroll
            for (int nt = 0; nt < 8; nt++) mma16816(s[nt], qh[ks], kl[nt]);
        }

        // ---- online softmax (log2 domain) ----
        float tA = -1e30f, tB = -1e30f;
#pragma unroll
        for (int nt = 0; nt < 8; nt++) {
            tA = fmaxf(tA, fmaxf(s[nt][0], s[nt][1]));
            tB = fmaxf(tB, fmaxf(s[nt][2], s[nt][3]));
        }
        tA = fmaxf(tA, __shfl_xor_sync(0xffffffff, tA, 1));
        tA = fmaxf(tA, __shfl_xor_sync(0xffffffff, tA, 2));
        tB = fmaxf(tB, __shfl_xor_sync(0xffffffff, tB, 1));
        tB = fmaxf(tB, __shfl_xor_sync(0xffffffff, tB, 2));
        float mnA = fmaxf(mA, tA), mnB = fmaxf(mB, tB);
        float cA = exp2f(mA - mnA), cB = exp2f(mB - mnB);
        lA *= cA; lB *= cB;
#pragma unroll
        for (int nt = 0; nt < 8; nt++) {
            o[nt][0] *= cA; o[nt][1] *= cA;
            o[nt][2] *= cB; o[nt][3] *= cB;
        }
        mA = mnA; mB = mnB;

        // ---- P = exp2(S - m), split hi/lo in registers ----
        uint32_t pAh[8], pAl[8], pBh[8], pBl[8];
#pragma unroll
        for (int nt = 0; nt < 8; nt++) {
            float p0 = exp2f(s[nt][0] - mnA);
            float p1 = exp2f(s[nt][1] - mnA);
            float p2 = exp2f(s[nt][2] - mnB);
            float p3 = exp2f(s[nt][3] - mnB);
            lA += p0 + p1; lB += p2 + p3;
            __half h0 = __float2half_rn(p0), h1 = __float2half_rn(p1);
            __half h2 = __float2half_rn(p2), h3 = __float2half_rn(p3);
            __half2 tt;
            tt.x = h0; tt.y = h1; pAh[nt] = *(uint32_t*)&tt;
            tt.x = h2; tt.y = h3; pBh[nt] = *(uint32_t*)&tt;
            tt.x = __float2half_rn(p0 - __half2float(h0));
            tt.y = __float2half_rn(p1 - __half2float(h1));
            pAl[nt] = *(uint32_t*)&tt;
            tt.x = __float2half_rn(p2 - __half2float(h2));
            tt.y = __float2half_rn(p3 - __half2float(h3));
            pBl[nt] = *(uint32_t*)&tt;
        }

        // ---- O += P . V ----
#pragma unroll
        for (int ks = 0; ks < 4; ks++) {
            uint32_t aPh[4] = { pAh[2 * ks], pBh[2 * ks], pAh[2 * ks + 1], pBh[2 * ks + 1] };
            uint32_t aPl[4] = { pAl[2 * ks], pBl[2 * ks], pAl[2 * ks + 1], pBl[2 * ks + 1] };
            uint32_t vh[8][2], vl[8][2];
#pragma unroll
            for (int ntd = 0; ntd < 8; ntd++) {
                uint32_t off = ((ks * 16 + (lane & 15)) * ST + ntd * 8) * 2;
                ldsm_x2_t(vh[ntd], uVh + off);
                ldsm_x2_t(vl[ntd], uVl + off);
            }
#pragma unroll
            for (int ntd = 0; ntd < 8; ntd++) mma16816(o[ntd], aPh, vh[ntd]);
#pragma unroll
            for (int ntd = 0; ntd < 8; ntd++) mma16816(o[ntd], aPl, vh[ntd]);
#pragma unroll
            for (int ntd = 0; ntd < 8; ntd++) mma16816(o[ntd], aPh, vl[ntd]);
        }
    }

    // ---- finalize ----
    lA += __shfl_xor_sync(0xffffffff, lA, 1);
    lA += __shfl_xor_sync(0xffffffff, lA, 2);
    lB += __shfl_xor_sync(0xffffffff, lB, 1);
    lB += __shfl_xor_sync(0xffffffff, lB, 2);
    float invA = 1.f / lA, invB = 1.f / lB;

    const int b = bh >> 4, h = bh & 15;
    const int rowA = q0 + w * 16 + (lane >> 2);
    const int rowB = rowA + 8;
    const int c2 = 2 * (lane & 3);
#pragma unroll
    for (int ntd = 0; ntd < 8; ntd++) {
        float v0 = o[ntd][0] * invA, v1 = o[ntd][1] * invA;
        float v2 = o[ntd][2] * invB, v3 = o[ntd][3] * invB;
        size_t offA = (size_t)(b * SEQ + rowA) * D_MODEL + h * D_K + ntd * 8 + c2;
        size_t offB = (size_t)(b * SEQ + rowB) * D_MODEL + h * D_K + ntd * 8 + c2;
        __half h0 = __float2half_rn(v0), h1 = __float2half_rn(v1);
        __half h2 = __float2half_rn(v2), h3 = __float2half_rn(v3);
        __half2 t2;
        t2.x = h0; t2.y = h1; *(__half2*)&Oh[offA] = t2;
        t2.x = __float2half_rn(v0 - __half2float(h0));
        t2.y = __float2half_rn(v1 - __half2float(h1));
        *(__half2*)&Ol[offA] = t2;
        t2.x = h2; t2.y = h3; *(__half2*)&Oh[offB] = t2;
        t2.x = __float2half_rn(v2 - __half2float(h2));
        t2.y = __float2half_rn(v3 - __half2float(h3));
        *(__half2*)&Ol[offB] = t2;
    }
}

// ---------------------------------------------------------------------------
// Launch: 4 kernels total -> ncu (-s 5 -c 1) lands on gemm_qkv.
// ---------------------------------------------------------------------------
extern "C" void kernel_launch(void* const* d_in, const int* in_sizes, int n_in,
                              void* d_out, int out_size)
{
    const float* q   = (const float*)d_in[0];
    const float* k   = (const float*)d_in[1];
    const float* v   = (const float*)d_in[2];
    const float* W_q = (const float*)d_in[3];
    const float* b_q = (const float*)d_in[4];
    const float* W_k = (const float*)d_in[5];
    const float* b_k = (const float*)d_in[6];
    const float* W_v = (const float*)d_in[7];
    const float* b_v = (const float*)d_in[8];
    const float* W_o = (const float*)d_in[9];
    const float* b_o = (const float*)d_in[10];
    float* out = (float*)d_out;

    __half* hf;
    cudaGetSymbolAddress((void**)&hf, g_hf);

    cudaFuncSetAttribute((void*)gemm_qkv, cudaFuncAttributeMaxDynamicSharedMemorySize, GSMEM);
    cudaFuncSetAttribute((void*)gemm_o,   cudaFuncAttributeMaxDynamicSharedMemorySize, GSMEM);
    cudaFuncSetAttribute((void*)flash_mma, cudaFuncAttributeMaxDynamicSharedMemorySize, FSMEM);

    // 1. fused split (7 tensors, 16384 blocks)
    SplitArgs sa;
    sa.src[0] = q;   sa.hi[0] = hf + OFF_IQH; sa.lo[0] = hf + OFF_IQL;
    sa.src[1] = k;   sa.hi[1] = hf + OFF_IKH; sa.lo[1] = hf + OFF_IKL;
    sa.src[2] = v;   sa.hi[2] = hf + OFF_IVH; sa.lo[2] = hf + OFF_IVL;
    sa.src[3] = W_q; sa.hi[3] = hf + OFF_WQH; sa.lo[3] = hf + OFF_WQL;
    sa.src[4] = W_k; sa.hi[4] = hf + OFF_WKH; sa.lo[4] = hf + OFF_WKL;
    sa.src[5] = W_v; sa.hi[5] = hf + OFF_WVH; sa.lo[5] = hf + OFF_WVL;
    sa.src[6] = W_o; sa.hi[6] = hf + OFF_WOH; sa.lo[6] = hf + OFF_WOL;
    split_all<<<16384, 256>>>(sa);

    // 2. fused QKV projections (grid z = 3)
    const float qscale = 0.125f * 1.4426950408889634f;
    GemmQKV gp;
    gp.g[0] = { hf + OFF_IQH, hf + OFF_IQL, hf + OFF_WQH, hf + OFF_WQL, b_q,
                hf + OFF_PQH, hf + OFF_PQL, nullptr, qscale };
    gp.g[1] = { hf + OFF_IKH, hf + OFF_IKL, hf + OFF_WKH, hf + OFF_WKL, b_k,
                hf + OFF_PKH, hf + OFF_PKL, nullptr, 1.0f };
    gp.g[2] = { hf + OFF_IVH, hf + OFF_IVL, hf + OFF_WVH, hf + OFF_WVL, b_v,
                hf + OFF_PVH, hf + OFF_PVL, nullptr, 1.0f };
    dim3 ggrid(D_MODEL / 128, M_TOK / 128, 3);   // (8, 32, 3) = 768 CTAs
    gemm_qkv<<<ggrid, 256, GSMEM>>>(gp);

    // 3. flash attention
    dim3 agrid(SEQ / 64, BSZ * N_HEADS);         // (32, 32)
    flash_mma<<<agrid, 128, FSMEM>>>(hf + OFF_PQH, hf + OFF_PQL,
                                     hf + OFF_PKH, hf + OFF_PKL,
                                     hf + OFF_PVH, hf + OFF_PVL,
                                     hf + OFF_OH, hf + OFF_OL);

    // 4. output projection
    GemmOne go = { hf + OFF_OH, hf + OFF_OL, hf + OFF_WOH, hf + OFF_WOL, b_o,
                   nullptr, nullptr, out, 1.0f };
    dim3 ogrid(D_MODEL / 128, M_TOK / 128, 1);
    gemm_o<<<ogrid, 256, GSMEM>>>(go);
}